// round 1
// baseline (speedup 1.0000x reference)
#include <cuda_runtime.h>
#include <cstddef>

// ---------------- problem constants ----------------
#define B_SZ   8
#define N_TOK  1024
#define C_DIM  768
#define H_NUM  12
#define D_HEAD 64
#define SCALE_Q 0.125f   // 64^-0.5

// ---------------- scratch (device globals; no cudaMalloc allowed) ----------------
__device__ float g_qkv[(size_t)B_SZ * N_TOK * 3 * C_DIM];   // [B,N,3,H,Dh] = 75.5 MB
__device__ float g_attn[(size_t)B_SZ * N_TOK * C_DIM];      // [B,N,H*Dh]   = 25.2 MB

// ============================================================
// SGEMM: C[M,N] = A[M,K] @ B[K,N] (+ bias[N] if has_bias)
// 128x128 block tile, K-tile 8, 256 threads, 8x8 microtile.
// Requires M%128==0, N%128==0, K%8==0 (true for all calls here).
// ============================================================
__global__ __launch_bounds__(256) void sgemm_kernel(
    const float* __restrict__ A, const float* __restrict__ Bm,
    const float* __restrict__ bias, float* __restrict__ C,
    int M, int N, int K, int has_bias)
{
    __shared__ float As[8][128];
    __shared__ float Bs[8][128];

    const int tid  = threadIdx.x;
    const int brow = blockIdx.y * 128;
    const int bcol = blockIdx.x * 128;
    const int ty = tid >> 4;          // 0..15
    const int tx = tid & 15;          // 0..15

    // A tile load map: 128 rows x 8 cols, one float4 per thread
    const int arow = tid >> 1;            // 0..127
    const int acol = (tid & 1) * 4;       // 0 or 4
    // B tile load map: 8 rows x 128 cols, one float4 per thread
    const int browl = tid >> 5;           // 0..7
    const int bcoll = (tid & 31) * 4;     // 0..124

    float acc[8][8];
#pragma unroll
    for (int i = 0; i < 8; i++)
#pragma unroll
        for (int j = 0; j < 8; j++) acc[i][j] = 0.f;

    for (int k0 = 0; k0 < K; k0 += 8) {
        float4 a4 = *(const float4*)&A[(size_t)(brow + arow) * K + k0 + acol];
        As[acol + 0][arow] = a4.x;
        As[acol + 1][arow] = a4.y;
        As[acol + 2][arow] = a4.z;
        As[acol + 3][arow] = a4.w;
        *(float4*)&Bs[browl][bcoll] =
            *(const float4*)&Bm[(size_t)(k0 + browl) * N + bcol + bcoll];
        __syncthreads();

#pragma unroll
        for (int kk = 0; kk < 8; kk++) {
            float af[8], bf[8];
            *(float4*)&af[0] = *(float4*)&As[kk][ty * 8];
            *(float4*)&af[4] = *(float4*)&As[kk][ty * 8 + 4];
            *(float4*)&bf[0] = *(float4*)&Bs[kk][tx * 8];
            *(float4*)&bf[4] = *(float4*)&Bs[kk][tx * 8 + 4];
#pragma unroll
            for (int i = 0; i < 8; i++)
#pragma unroll
                for (int j = 0; j < 8; j++)
                    acc[i][j] = fmaf(af[i], bf[j], acc[i][j]);
        }
        __syncthreads();
    }

#pragma unroll
    for (int i = 0; i < 8; i++) {
        const size_t r = (size_t)(brow + ty * 8 + i);
#pragma unroll
        for (int j = 0; j < 8; j += 4) {
            const int c = bcol + tx * 8 + j;
            float4 v = make_float4(acc[i][j], acc[i][j + 1], acc[i][j + 2], acc[i][j + 3]);
            if (has_bias) {
                v.x += __ldg(&bias[c + 0]);
                v.y += __ldg(&bias[c + 1]);
                v.z += __ldg(&bias[c + 2]);
                v.w += __ldg(&bias[c + 3]);
            }
            *(float4*)&C[r * N + c] = v;
        }
    }
}

// ============================================================
// Fused Taylor attention (one pass, no NxN materialization).
// grid = (N_TOK/64, B*H), block = 256.
// f(s) = 1 + s + s^2/2  (>0 always, so relu is a no-op; denom > 0)
// out[b,n,h,d] = (sum_m f(q.k) * v[m,d]) / (sum_m f(q.k))
// smem (dynamic): qs,ks,vs,ps each [64][68] + denom[64]
// ============================================================
#define PAD 68
#define ATTN_SMEM_BYTES ((4 * 64 * PAD + 64) * sizeof(float))

__global__ __launch_bounds__(256) void attn_kernel(
    const float* __restrict__ qkv, float* __restrict__ out)
{
    extern __shared__ float smem[];
    float (*qs)[PAD] = (float(*)[PAD])(smem);
    float (*ks)[PAD] = (float(*)[PAD])(smem + 64 * PAD);
    float (*vs)[PAD] = (float(*)[PAD])(smem + 2 * 64 * PAD);
    float (*ps)[PAD] = (float(*)[PAD])(smem + 3 * 64 * PAD);
    float* denom     = smem + 4 * 64 * PAD;

    const int tid  = threadIdx.x;
    const int bh   = blockIdx.y;
    const int b    = bh / H_NUM;
    const int h    = bh % H_NUM;
    const int row0 = blockIdx.x * 64;
    const int ty = tid >> 4;   // 0..15 -> rows ty*4..+3
    const int tx = tid & 15;   // 0..15 -> cols tx*4..+3

    // load Q tile (pre-scaled)
    for (int i = tid; i < 64 * D_HEAD; i += 256) {
        const int r = i >> 6, d = i & 63;
        const size_t off = ((size_t)(b * N_TOK + row0 + r) * 3 + 0) * C_DIM + h * D_HEAD + d;
        qs[r][d] = qkv[off] * SCALE_Q;
    }
    if (tid < 64) denom[tid] = 0.f;

    float acc[4][4];
#pragma unroll
    for (int i = 0; i < 4; i++)
#pragma unroll
        for (int j = 0; j < 4; j++) acc[i][j] = 0.f;

    for (int m0 = 0; m0 < N_TOK; m0 += 64) {
        __syncthreads();   // protects ks/vs/ps reuse (also covers initial q load)
        for (int i = tid; i < 64 * D_HEAD; i += 256) {
            const int r = i >> 6, d = i & 63;
            const size_t nb = (size_t)(b * N_TOK + m0 + r) * 3;
            ks[r][d] = qkv[(nb + 1) * C_DIM + h * D_HEAD + d];
            vs[r][d] = qkv[(nb + 2) * C_DIM + h * D_HEAD + d];
        }
        __syncthreads();

        // S = Q K^T  (4x4 per thread)
        float s[4][4];
#pragma unroll
        for (int i = 0; i < 4; i++)
#pragma unroll
            for (int j = 0; j < 4; j++) s[i][j] = 0.f;

#pragma unroll 8
        for (int d = 0; d < D_HEAD; d++) {
            float qf[4], kf[4];
#pragma unroll
            for (int i = 0; i < 4; i++) qf[i] = qs[ty * 4 + i][d];
#pragma unroll
            for (int j = 0; j < 4; j++) kf[j] = ks[tx * 4 + j][d];
#pragma unroll
            for (int i = 0; i < 4; i++)
#pragma unroll
                for (int j = 0; j < 4; j++) s[i][j] = fmaf(qf[i], kf[j], s[i][j]);
        }

        // f(s) -> ps (float4 row stores)
#pragma unroll
        for (int i = 0; i < 4; i++) {
            float4 f4;
            float v;
            v = s[i][0]; f4.x = fmaxf(fmaf(0.5f * v, v, 1.f + v), 0.f);
            v = s[i][1]; f4.y = fmaxf(fmaf(0.5f * v, v, 1.f + v), 0.f);
            v = s[i][2]; f4.z = fmaxf(fmaf(0.5f * v, v, 1.f + v), 0.f);
            v = s[i][3]; f4.w = fmaxf(fmaf(0.5f * v, v, 1.f + v), 0.f);
            *(float4*)&ps[ty * 4 + i][tx * 4] = f4;
        }
        __syncthreads();

        // row sums -> denom
        if (tid < 64) {
            float sum = 0.f;
#pragma unroll 8
            for (int c = 0; c < 64; c++) sum += ps[tid][c];
            denom[tid] += sum;
        }

        // acc += P @ V  (4x4 per thread)
#pragma unroll 4
        for (int kk = 0; kk < 64; kk++) {
            float pf[4];
#pragma unroll
            for (int i = 0; i < 4; i++) pf[i] = ps[ty * 4 + i][kk];
            const float4 vf = *(const float4*)&vs[kk][tx * 4];
#pragma unroll
            for (int i = 0; i < 4; i++) {
                acc[i][0] = fmaf(pf[i], vf.x, acc[i][0]);
                acc[i][1] = fmaf(pf[i], vf.y, acc[i][1]);
                acc[i][2] = fmaf(pf[i], vf.z, acc[i][2]);
                acc[i][3] = fmaf(pf[i], vf.w, acc[i][3]);
            }
        }
    }
    __syncthreads();

    // out[b, row, h*64 + col] = acc / denom[row]
#pragma unroll
    for (int i = 0; i < 4; i++) {
        const int r = ty * 4 + i;
        const float inv = __frcp_rn(denom[r]);
        const size_t base = (size_t)(b * N_TOK + row0 + r) * C_DIM + h * D_HEAD + tx * 4;
        float4 o = make_float4(acc[i][0] * inv, acc[i][1] * inv,
                               acc[i][2] * inv, acc[i][3] * inv);
        *(float4*)&out[base] = o;
    }
}

// ============================================================
// launcher
// ============================================================
extern "C" void kernel_launch(void* const* d_in, const int* in_sizes, int n_in,
                              void* d_out, int out_size)
{
    const float* x      = (const float*)d_in[0];
    const float* w_qkv  = (const float*)d_in[1];
    const float* w_proj = (const float*)d_in[2];
    const float* b_proj = (const float*)d_in[3];
    float* out = (float*)d_out;

    float *qkv_s = nullptr, *attn_s = nullptr;
    cudaGetSymbolAddress((void**)&qkv_s, g_qkv);
    cudaGetSymbolAddress((void**)&attn_s, g_attn);
    cudaFuncSetAttribute(attn_kernel, cudaFuncAttributeMaxDynamicSharedMemorySize,
                         (int)ATTN_SMEM_BYTES);

    const int M = B_SZ * N_TOK;           // 8192

    // 1) qkv = x @ w_qkv      [8192,768] @ [768,2304]
    sgemm_kernel<<<dim3((3 * C_DIM) / 128, M / 128), 256>>>(
        x, w_qkv, nullptr, qkv_s, M, 3 * C_DIM, C_DIM, 0);

    // 2) fused Taylor attention -> [B,N,C]
    attn_kernel<<<dim3(N_TOK / 64, B_SZ * H_NUM), 256, ATTN_SMEM_BYTES>>>(qkv_s, attn_s);

    // 3) out = attn @ w_proj + b_proj    [8192,768] @ [768,768]
    sgemm_kernel<<<dim3(C_DIM / 128, M / 128), 256>>>(
        attn_s, w_proj, b_proj, out, M, C_DIM, C_DIM, 1);
}

// round 2
// speedup vs baseline: 2.8928x; 2.8928x over previous
#include <cuda_runtime.h>
#include <cstdint>
#include <cstddef>

// ---------------- problem constants ----------------
#define B_SZ   8
#define N_TOK  1024
#define C_DIM  768
#define H_NUM  12
#define D_HEAD 64
#define SCALE_Q 0.125f   // 64^-0.5

// ---------------- scratch (device globals; no cudaMalloc allowed) ----------------
__device__ float g_qkv[(size_t)B_SZ * N_TOK * 3 * C_DIM];   // [B,N,3,H*Dh]
__device__ float g_attn[(size_t)B_SZ * N_TOK * C_DIM];      // [B,N,H*Dh]

// ---------------- tf32 helpers ----------------
__device__ __forceinline__ float f2tf32(float x) {
    uint32_t u;
    asm("cvt.rna.tf32.f32 %0, %1;" : "=r"(u) : "f"(x));
    return __uint_as_float(u);
}

// d += a(16x8, tf32, row) * b(8x8, tf32, col)
__device__ __forceinline__ void mma_tf32(float* d, const uint32_t* a, const uint32_t* b) {
    asm volatile(
        "mma.sync.aligned.m16n8k8.row.col.f32.tf32.tf32.f32 "
        "{%0,%1,%2,%3}, {%4,%5,%6,%7}, {%8,%9}, {%0,%1,%2,%3};"
        : "+f"(d[0]), "+f"(d[1]), "+f"(d[2]), "+f"(d[3])
        : "r"(a[0]), "r"(a[1]), "r"(a[2]), "r"(a[3]),
          "r"(b[0]), "r"(b[1]));
}

// ============================================================
// TF32 GEMM: C[M,N] = A[M,K] @ B[K,N] (+bias). 128x128x16 tile,
// 256 threads / 8 warps, warp = 64x32 (4x4 m16n8 tiles).
// Requires M%128==0, N%128==0, K%16==0.
// ============================================================
#define GPAD_A 20   // 16+4
#define GPAD_B 132  // 128+4

__global__ __launch_bounds__(256) void gemm_tf32(
    const float* __restrict__ A, const float* __restrict__ Bm,
    const float* __restrict__ bias, float* __restrict__ C,
    int M, int N, int K, int has_bias)
{
    __shared__ float As[128][GPAD_A];
    __shared__ float Bs[16][GPAD_B];

    const int tid  = threadIdx.x;
    const int wid  = tid >> 5;
    const int lane = tid & 31;
    const int grp  = lane >> 2;   // 0..7
    const int qd   = lane & 3;    // 0..3

    const int brow = blockIdx.y * 128;
    const int bcol = blockIdx.x * 128;
    const int m_base = (wid & 1) * 64;   // warp row offset in block
    const int n_base = (wid >> 1) * 32;  // warp col offset in block

    float acc[4][4][4];
#pragma unroll
    for (int i = 0; i < 4; i++)
#pragma unroll
        for (int j = 0; j < 4; j++)
#pragma unroll
            for (int t = 0; t < 4; t++) acc[i][j][t] = 0.f;

    for (int k0 = 0; k0 < K; k0 += 16) {
        // A tile: 128 rows x 16 cols
#pragma unroll
        for (int l = 0; l < 2; l++) {
            const int idx = tid + l * 256;
            const int r = idx >> 2, c4 = (idx & 3) * 4;
            float4 v = *(const float4*)&A[(size_t)(brow + r) * K + k0 + c4];
            As[r][c4 + 0] = f2tf32(v.x);
            As[r][c4 + 1] = f2tf32(v.y);
            As[r][c4 + 2] = f2tf32(v.z);
            As[r][c4 + 3] = f2tf32(v.w);
        }
        // B tile: 16 rows x 128 cols
#pragma unroll
        for (int l = 0; l < 2; l++) {
            const int idx = tid + l * 256;
            const int r = idx >> 5, c4 = (idx & 31) * 4;
            float4 v = *(const float4*)&Bm[(size_t)(k0 + r) * N + bcol + c4];
            Bs[r][c4 + 0] = f2tf32(v.x);
            Bs[r][c4 + 1] = f2tf32(v.y);
            Bs[r][c4 + 2] = f2tf32(v.z);
            Bs[r][c4 + 3] = f2tf32(v.w);
        }
        __syncthreads();

#pragma unroll
        for (int ks = 0; ks < 16; ks += 8) {
            uint32_t af[4][4];
#pragma unroll
            for (int mt = 0; mt < 4; mt++) {
                const int row = m_base + mt * 16;
                af[mt][0] = __float_as_uint(As[row + grp    ][ks + qd    ]);
                af[mt][1] = __float_as_uint(As[row + grp + 8][ks + qd    ]);
                af[mt][2] = __float_as_uint(As[row + grp    ][ks + qd + 4]);
                af[mt][3] = __float_as_uint(As[row + grp + 8][ks + qd + 4]);
            }
#pragma unroll
            for (int nt = 0; nt < 4; nt++) {
                const int col = n_base + nt * 8 + grp;
                uint32_t bf[2];
                bf[0] = __float_as_uint(Bs[ks + qd    ][col]);
                bf[1] = __float_as_uint(Bs[ks + qd + 4][col]);
#pragma unroll
                for (int mt = 0; mt < 4; mt++)
                    mma_tf32(acc[mt][nt], af[mt], bf);
            }
        }
        __syncthreads();
    }

    // store
#pragma unroll
    for (int mt = 0; mt < 4; mt++) {
        const int r1 = brow + m_base + mt * 16 + grp;
        const int r2 = r1 + 8;
#pragma unroll
        for (int nt = 0; nt < 4; nt++) {
            const int c = bcol + n_base + nt * 8 + 2 * qd;
            float b0 = 0.f, b1 = 0.f;
            if (has_bias) { b0 = __ldg(&bias[c]); b1 = __ldg(&bias[c + 1]); }
            float2 o1 = make_float2(acc[mt][nt][0] + b0, acc[mt][nt][1] + b1);
            float2 o2 = make_float2(acc[mt][nt][2] + b0, acc[mt][nt][3] + b1);
            *(float2*)&C[(size_t)r1 * N + c] = o1;
            *(float2*)&C[(size_t)r2 * N + c] = o2;
        }
    }
}

// ============================================================
// Fused Taylor attention, tf32 tensor cores.
// grid = (16, 96), block = 256 (8 warps).
// Q tile 64 rows; K/V streamed in 128-row tiles.
// S phase: warp -> 16x64 of S (rows 16*(w&3), cols 64*(w>>2))
// PV phase: warp -> 16x32 of O (rows 16*(w&3), cols 32*(w>>2))
// ============================================================
#define APAD   68    // 64+4
#define PPAD   132   // 128+4
#define QS_OFF 0
#define KS_OFF (64 * APAD)
#define VS_OFF (KS_OFF + 128 * APAD)
#define PS_OFF (VS_OFF + 128 * APAD)
#define DN_OFF (PS_OFF + 64 * PPAD)
#define ATTN_SMEM_FLOATS (DN_OFF + 64)
#define ATTN_SMEM_BYTES  (ATTN_SMEM_FLOATS * sizeof(float))

__global__ __launch_bounds__(256) void attn_tf32(
    const float* __restrict__ qkv, float* __restrict__ out)
{
    extern __shared__ float smem[];
    float (*qs)[APAD] = (float(*)[APAD])(smem + QS_OFF);
    float (*ks)[APAD] = (float(*)[APAD])(smem + KS_OFF);
    float (*vs)[APAD] = (float(*)[APAD])(smem + VS_OFF);
    float (*ps)[PPAD] = (float(*)[PPAD])(smem + PS_OFF);
    float* denom      = smem + DN_OFF;

    const int tid  = threadIdx.x;
    const int wid  = tid >> 5;
    const int lane = tid & 31;
    const int grp  = lane >> 2;
    const int qd   = lane & 3;

    const int b    = blockIdx.y / H_NUM;
    const int h    = blockIdx.y % H_NUM;
    const int row0 = blockIdx.x * 64;

    const int sm_row = (wid & 3) * 16;   // S-phase / PV-phase row base
    const int sn0    = (wid >> 2) * 64;  // S-phase col base
    const int on0    = (wid >> 2) * 32;  // PV-phase col base

    // ---- load Q tile (scaled, tf32) ----
#pragma unroll
    for (int l = 0; l < 4; l++) {
        const int idx = tid + l * 256;
        const int r = idx >> 4, c4 = (idx & 15) * 4;
        const size_t off = ((size_t)(b * N_TOK + row0 + r) * 3) * C_DIM + h * D_HEAD + c4;
        float4 v = *(const float4*)&qkv[off];
        qs[r][c4 + 0] = f2tf32(v.x * SCALE_Q);
        qs[r][c4 + 1] = f2tf32(v.y * SCALE_Q);
        qs[r][c4 + 2] = f2tf32(v.z * SCALE_Q);
        qs[r][c4 + 3] = f2tf32(v.w * SCALE_Q);
    }
    if (tid < 64) denom[tid] = 0.f;

    float acc_o[4][4];
#pragma unroll
    for (int i = 0; i < 4; i++)
#pragma unroll
        for (int t = 0; t < 4; t++) acc_o[i][t] = 0.f;

    for (int m0 = 0; m0 < N_TOK; m0 += 128) {
        __syncthreads();   // protect ks/vs/ps reuse (covers initial Q/denom too)
        // ---- load K,V tiles (128 x 64 each) ----
#pragma unroll
        for (int l = 0; l < 8; l++) {
            const int idx = tid + l * 256;
            const int r = idx >> 4, c4 = (idx & 15) * 4;
            const size_t base = ((size_t)(b * N_TOK + m0 + r) * 3) * C_DIM + h * D_HEAD + c4;
            float4 kv = *(const float4*)&qkv[base + C_DIM];
            float4 vv = *(const float4*)&qkv[base + 2 * C_DIM];
            ks[r][c4 + 0] = f2tf32(kv.x); ks[r][c4 + 1] = f2tf32(kv.y);
            ks[r][c4 + 2] = f2tf32(kv.z); ks[r][c4 + 3] = f2tf32(kv.w);
            vs[r][c4 + 0] = f2tf32(vv.x); vs[r][c4 + 1] = f2tf32(vv.y);
            vs[r][c4 + 2] = f2tf32(vv.z); vs[r][c4 + 3] = f2tf32(vv.w);
        }
        __syncthreads();

        // ---- S = Q @ K^T : warp computes 16x64 ----
        float acc_s[8][4];
#pragma unroll
        for (int i = 0; i < 8; i++)
#pragma unroll
            for (int t = 0; t < 4; t++) acc_s[i][t] = 0.f;

#pragma unroll
        for (int kk = 0; kk < 64; kk += 8) {
            uint32_t af[4];
            af[0] = __float_as_uint(qs[sm_row + grp    ][kk + qd    ]);
            af[1] = __float_as_uint(qs[sm_row + grp + 8][kk + qd    ]);
            af[2] = __float_as_uint(qs[sm_row + grp    ][kk + qd + 4]);
            af[3] = __float_as_uint(qs[sm_row + grp + 8][kk + qd + 4]);
#pragma unroll
            for (int nt = 0; nt < 8; nt++) {
                const int n = sn0 + nt * 8 + grp;
                uint32_t bf[2];
                bf[0] = __float_as_uint(ks[n][kk + qd    ]);
                bf[1] = __float_as_uint(ks[n][kk + qd + 4]);
                mma_tf32(acc_s[nt], af, bf);
            }
        }

        // ---- f(s) = 1 + s + s^2/2 (always > 0), stage P, row sums ----
        float rs1 = 0.f, rs2 = 0.f;
        const int r1 = sm_row + grp, r2 = r1 + 8;
#pragma unroll
        for (int nt = 0; nt < 8; nt++) {
            float fx, fy, fz, fw, v;
            v = acc_s[nt][0]; fx = fmaf(0.5f * v, v, 1.f + v);
            v = acc_s[nt][1]; fy = fmaf(0.5f * v, v, 1.f + v);
            v = acc_s[nt][2]; fz = fmaf(0.5f * v, v, 1.f + v);
            v = acc_s[nt][3]; fw = fmaf(0.5f * v, v, 1.f + v);
            rs1 += fx + fy;
            rs2 += fz + fw;
            const int col = sn0 + nt * 8 + 2 * qd;
            *(float2*)&ps[r1][col] = make_float2(f2tf32(fx), f2tf32(fy));
            *(float2*)&ps[r2][col] = make_float2(f2tf32(fz), f2tf32(fw));
        }
        rs1 += __shfl_xor_sync(0xffffffffu, rs1, 1);
        rs1 += __shfl_xor_sync(0xffffffffu, rs1, 2);
        rs2 += __shfl_xor_sync(0xffffffffu, rs2, 1);
        rs2 += __shfl_xor_sync(0xffffffffu, rs2, 2);
        if (qd == 0) {
            atomicAdd(&denom[r1], rs1);
            atomicAdd(&denom[r2], rs2);
        }
        __syncthreads();

        // ---- O += P @ V : warp computes 16x32, k=128 ----
#pragma unroll
        for (int kk = 0; kk < 128; kk += 8) {
            uint32_t af[4];
            af[0] = __float_as_uint(ps[sm_row + grp    ][kk + qd    ]);
            af[1] = __float_as_uint(ps[sm_row + grp + 8][kk + qd    ]);
            af[2] = __float_as_uint(ps[sm_row + grp    ][kk + qd + 4]);
            af[3] = __float_as_uint(ps[sm_row + grp + 8][kk + qd + 4]);
#pragma unroll
            for (int nt = 0; nt < 4; nt++) {
                const int col = on0 + nt * 8 + grp;
                uint32_t bf[2];
                bf[0] = __float_as_uint(vs[kk + qd    ][col]);
                bf[1] = __float_as_uint(vs[kk + qd + 4][col]);
                mma_tf32(acc_o[nt], af, bf);
            }
        }
    }
    __syncthreads();

    // ---- normalize + store ----
    const int r1 = sm_row + grp, r2 = r1 + 8;
    const float inv1 = 1.f / denom[r1];
    const float inv2 = 1.f / denom[r2];
#pragma unroll
    for (int nt = 0; nt < 4; nt++) {
        const int c = h * D_HEAD + on0 + nt * 8 + 2 * qd;
        const size_t base1 = (size_t)(b * N_TOK + row0 + r1) * C_DIM + c;
        const size_t base2 = (size_t)(b * N_TOK + row0 + r2) * C_DIM + c;
        *(float2*)&out[base1] = make_float2(acc_o[nt][0] * inv1, acc_o[nt][1] * inv1);
        *(float2*)&out[base2] = make_float2(acc_o[nt][2] * inv2, acc_o[nt][3] * inv2);
    }
}

// ============================================================
// launcher
// ============================================================
extern "C" void kernel_launch(void* const* d_in, const int* in_sizes, int n_in,
                              void* d_out, int out_size)
{
    const float* x      = (const float*)d_in[0];
    const float* w_qkv  = (const float*)d_in[1];
    const float* w_proj = (const float*)d_in[2];
    const float* b_proj = (const float*)d_in[3];
    float* out = (float*)d_out;

    float *qkv_s = nullptr, *attn_s = nullptr;
    cudaGetSymbolAddress((void**)&qkv_s, g_qkv);
    cudaGetSymbolAddress((void**)&attn_s, g_attn);
    cudaFuncSetAttribute(attn_tf32, cudaFuncAttributeMaxDynamicSharedMemorySize,
                         (int)ATTN_SMEM_BYTES);

    const int M = B_SZ * N_TOK;  // 8192

    // 1) qkv = x @ w_qkv      [8192,768] @ [768,2304]
    gemm_tf32<<<dim3((3 * C_DIM) / 128, M / 128), 256>>>(
        x, w_qkv, nullptr, qkv_s, M, 3 * C_DIM, C_DIM, 0);

    // 2) fused Taylor attention -> [B,N,C]
    attn_tf32<<<dim3(N_TOK / 64, B_SZ * H_NUM), 256, ATTN_SMEM_BYTES>>>(qkv_s, attn_s);

    // 3) out = attn @ w_proj + b_proj    [8192,768] @ [768,768]
    gemm_tf32<<<dim3(C_DIM / 128, M / 128), 256>>>(
        attn_s, w_proj, b_proj, out, M, C_DIM, C_DIM, 1);
}

// round 3
// speedup vs baseline: 3.8632x; 1.3354x over previous
#include <cuda_runtime.h>
#include <cstdint>
#include <cstddef>

// ---------------- problem constants ----------------
#define B_SZ   8
#define N_TOK  1024
#define C_DIM  768
#define H_NUM  12
#define D_HEAD 64
#define SCALE_Q 0.125f   // 64^-0.5

// ---------------- scratch (device globals; no cudaMalloc allowed) ----------------
__device__ float g_qkv[(size_t)B_SZ * N_TOK * 3 * C_DIM];   // [B,N,3,H*Dh]
__device__ float g_attn[(size_t)B_SZ * N_TOK * C_DIM];      // [B,N,H*Dh]

// ---------------- helpers ----------------
__device__ __forceinline__ float f2tf32(float x) {
    uint32_t u;
    asm("cvt.rna.tf32.f32 %0, %1;" : "=r"(u) : "f"(x));
    return __uint_as_float(u);
}

// d += a(16x8 tf32, row-major) * b(8x8 tf32, col-major)
__device__ __forceinline__ void mma_tf32(float* d, const uint32_t* a, const uint32_t* b) {
    asm volatile(
        "mma.sync.aligned.m16n8k8.row.col.f32.tf32.tf32.f32 "
        "{%0,%1,%2,%3}, {%4,%5,%6,%7}, {%8,%9}, {%0,%1,%2,%3};"
        : "+f"(d[0]), "+f"(d[1]), "+f"(d[2]), "+f"(d[3])
        : "r"(a[0]), "r"(a[1]), "r"(a[2]), "r"(a[3]),
          "r"(b[0]), "r"(b[1]));
}

// ldmatrix x4 (b16 view): 4 regs. For tf32, each 8x8 b16 matrix = 8 rows x 4 tf32.
__device__ __forceinline__ void ldsm_x4(uint32_t* r, const float* p) {
    uint32_t addr = (uint32_t)__cvta_generic_to_shared(p);
    asm volatile(
        "ldmatrix.sync.aligned.m8n8.x4.shared.b16 {%0,%1,%2,%3}, [%4];"
        : "=r"(r[0]), "=r"(r[1]), "=r"(r[2]), "=r"(r[3]) : "r"(addr));
}

// A-fragment (m16k8) lane address offsets within a 16-row x 8-col tf32 tile:
//   row = base + (lane & 15), col = ks + ((lane>>4)<<2)
// B-fragment pair (two n8k8 tiles) from [n][k]-stored tile:
//   row = nbase + ntp*16 + ((lane>>4)<<3) + (lane&7), col = ks + (((lane>>3)&1)<<2)

// ============================================================
// TF32 GEMM: C[M,N] = A[M,K] @ B[K,N] (+bias). 128x128x16 tile,
// double-buffered smem, ldmatrix fragments, 8 warps (warp 64x32).
// Requires M%128==0, N%128==0, K%16==0.
// ============================================================
#define GT_PAD 20   // 16 + 4 floats -> 80B row pitch (odd multiple of 16B)

__global__ __launch_bounds__(256, 2) void gemm_tf32(
    const float* __restrict__ A, const float* __restrict__ Bm,
    const float* __restrict__ bias, float* __restrict__ C,
    int M, int N, int K, int has_bias)
{
    __shared__ float As[2][128][GT_PAD];      // [row][k]
    __shared__ float Bt[2][128][GT_PAD];      // [n][k]  (transposed)

    const int tid  = threadIdx.x;
    const int wid  = tid >> 5;
    const int lane = tid & 31;
    const int grp  = lane >> 2;
    const int qd   = lane & 3;

    const int brow = blockIdx.y * 128;
    const int bcol = blockIdx.x * 128;
    const int m_base = (wid & 1) * 64;
    const int n_base = (wid >> 1) * 32;

    // gmem->reg load mapping
    const int ar0 = (tid * 2) >> 2;          // via idx = tid*2 + l
    // A: idx = tid + l*256 -> r = idx>>2, c4 = (idx&3)*4
    // B: threads 0..127 -> khalf 0, 128..255 -> khalf 8; n = tid & 127
    const int nB    = tid & 127;
    const int khalf = (tid >> 7) * 8;
    (void)ar0;

    float4 a_pre[2];
    float  b_pre[8];

    float acc[4][4][4];
#pragma unroll
    for (int i = 0; i < 4; i++)
#pragma unroll
        for (int j = 0; j < 4; j++)
#pragma unroll
            for (int t = 0; t < 4; t++) acc[i][j][t] = 0.f;

    auto load_gmem = [&](int k0) {
#pragma unroll
        for (int l = 0; l < 2; l++) {
            const int idx = tid + l * 256;
            a_pre[l] = *(const float4*)&A[(size_t)(brow + (idx >> 2)) * K + k0 + (idx & 3) * 4];
        }
#pragma unroll
        for (int j = 0; j < 8; j++)
            b_pre[j] = Bm[(size_t)(k0 + khalf + j) * N + bcol + nB];
    };

    auto store_smem = [&](int buf) {
#pragma unroll
        for (int l = 0; l < 2; l++) {
            const int idx = tid + l * 256;
            float* dst = &As[buf][idx >> 2][(idx & 3) * 4];
            dst[0] = f2tf32(a_pre[l].x); dst[1] = f2tf32(a_pre[l].y);
            dst[2] = f2tf32(a_pre[l].z); dst[3] = f2tf32(a_pre[l].w);
        }
        float* db = &Bt[buf][nB][khalf];
#pragma unroll
        for (int j = 0; j < 8; j++) db[j] = f2tf32(b_pre[j]);
    };

    auto compute = [&](int buf) {
#pragma unroll
        for (int ks = 0; ks < 16; ks += 8) {
            uint32_t af[4][4];
#pragma unroll
            for (int mt = 0; mt < 4; mt++)
                ldsm_x4(af[mt], &As[buf][m_base + mt * 16 + (lane & 15)][ks + ((lane >> 4) << 2)]);
            uint32_t bf[2][4];
#pragma unroll
            for (int ntp = 0; ntp < 2; ntp++)
                ldsm_x4(bf[ntp], &Bt[buf][n_base + ntp * 16 + ((lane >> 4) << 3) + (lane & 7)]
                                         [ks + (((lane >> 3) & 1) << 2)]);
#pragma unroll
            for (int nt = 0; nt < 4; nt++) {
                const uint32_t* bb = &bf[nt >> 1][(nt & 1) * 2];
#pragma unroll
                for (int mt = 0; mt < 4; mt++)
                    mma_tf32(acc[mt][nt], af[mt], bb);
            }
        }
    };

    const int T = K / 16;
    load_gmem(0);
    store_smem(0);
    __syncthreads();

    for (int t = 0; t < T; t++) {
        const int buf = t & 1;
        if (t + 1 < T) load_gmem((t + 1) * 16);
        compute(buf);
        if (t + 1 < T) store_smem(buf ^ 1);
        __syncthreads();
    }

    // epilogue
#pragma unroll
    for (int mt = 0; mt < 4; mt++) {
        const int r1 = brow + m_base + mt * 16 + grp;
        const int r2 = r1 + 8;
#pragma unroll
        for (int nt = 0; nt < 4; nt++) {
            const int c = bcol + n_base + nt * 8 + 2 * qd;
            float b0 = 0.f, b1 = 0.f;
            if (has_bias) { b0 = __ldg(&bias[c]); b1 = __ldg(&bias[c + 1]); }
            *(float2*)&C[(size_t)r1 * N + c] =
                make_float2(acc[mt][nt][0] + b0, acc[mt][nt][1] + b1);
            *(float2*)&C[(size_t)r2 * N + c] =
                make_float2(acc[mt][nt][2] + b0, acc[mt][nt][3] + b1);
        }
    }
}

// ============================================================
// Fused Taylor attention, tf32 + ldmatrix. Q tile = 128 rows.
// grid = (8, 96), block = 256 (8 warps).
// S phase: warp -> 32x64 of S (rows (w&3)*32, cols (w>>2)*64)
// PV phase: warp -> 16x64 of O (rows w*16)
// f(s) = 1 + s + s^2/2 > 0 (relu no-op); denom via shfl+atomic.
// ============================================================
#define QROWS 128
#define KTILE 128
#define APAD  68    // 17 x 16B (odd) for qs/ks
#define VPAD  132   // 33 x 16B (odd) for vs_t/ps

#define QS_OFF 0
#define KS_OFF (QS_OFF + QROWS * APAD)
#define VT_OFF (KS_OFF + KTILE * APAD)
#define PS_OFF (VT_OFF + D_HEAD * VPAD)
#define DN_OFF (PS_OFF + QROWS * VPAD)
#define ATTN_SMEM_FLOATS (DN_OFF + QROWS)
#define ATTN_SMEM_BYTES  (ATTN_SMEM_FLOATS * sizeof(float))

__global__ __launch_bounds__(256, 1) void attn_tf32(
    const float* __restrict__ qkv, float* __restrict__ out)
{
    extern __shared__ float smem[];
    float (*qs)[APAD]  = (float(*)[APAD])(smem + QS_OFF);   // [qrow][d]
    float (*ks)[APAD]  = (float(*)[APAD])(smem + KS_OFF);   // [krow][d]
    float (*vt)[VPAD]  = (float(*)[VPAD])(smem + VT_OFF);   // [d][krow] (transposed)
    float (*ps)[VPAD]  = (float(*)[VPAD])(smem + PS_OFF);   // [qrow][krow]
    float* denom       = smem + DN_OFF;

    const int tid  = threadIdx.x;
    const int wid  = tid >> 5;
    const int lane = tid & 31;
    const int grp  = lane >> 2;
    const int qd   = lane & 3;

    const int b    = blockIdx.y / H_NUM;
    const int h    = blockIdx.y % H_NUM;
    const int row0 = blockIdx.x * QROWS;

    const int sm0 = (wid & 3) * 32;    // S-phase row base (32 rows)
    const int sc0 = (wid >> 2) * 64;   // S-phase col base (64 cols)
    const int pm0 = wid * 16;          // PV-phase row base (16 rows)

    // ---- load Q tile (scaled, tf32) : 128x64 ----
#pragma unroll
    for (int l = 0; l < 8; l++) {
        const int idx = tid + l * 256;
        const int r = idx >> 4, c4 = (idx & 15) * 4;
        const size_t off = ((size_t)(b * N_TOK + row0 + r) * 3) * C_DIM + h * D_HEAD + c4;
        float4 v = *(const float4*)&qkv[off];
        qs[r][c4 + 0] = f2tf32(v.x * SCALE_Q);
        qs[r][c4 + 1] = f2tf32(v.y * SCALE_Q);
        qs[r][c4 + 2] = f2tf32(v.z * SCALE_Q);
        qs[r][c4 + 3] = f2tf32(v.w * SCALE_Q);
    }
    if (tid < QROWS) denom[tid] = 0.f;

    float acc_o[8][4];
#pragma unroll
    for (int i = 0; i < 8; i++)
#pragma unroll
        for (int t = 0; t < 4; t++) acc_o[i][t] = 0.f;

    // V transpose-load mapping: d = tid&63, sel = tid>>6
    const int vd  = tid & 63;
    const int sel = tid >> 6;

    for (int m0 = 0; m0 < N_TOK; m0 += KTILE) {
        __syncthreads();   // protect ks/vt/ps reuse (covers Q/denom on iter 0)

        // ---- K tile: [128][64], row-major float4 loads ----
#pragma unroll
        for (int l = 0; l < 8; l++) {
            const int idx = tid + l * 256;
            const int r = idx >> 4, c4 = (idx & 15) * 4;
            const size_t base = ((size_t)(b * N_TOK + m0 + r) * 3 + 1) * C_DIM + h * D_HEAD + c4;
            float4 v = *(const float4*)&qkv[base];
            ks[r][c4 + 0] = f2tf32(v.x); ks[r][c4 + 1] = f2tf32(v.y);
            ks[r][c4 + 2] = f2tf32(v.z); ks[r][c4 + 3] = f2tf32(v.w);
        }
        // ---- V tile transposed: vt[d][m], scalar LDG (coalesced) + float4 STS ----
#pragma unroll
        for (int g = 0; g < 8; g++) {
            const int m = g * 16 + sel * 4;
            const size_t base = ((size_t)(b * N_TOK + m0 + m) * 3 + 2) * C_DIM + h * D_HEAD + vd;
            const size_t str  = (size_t)3 * C_DIM;
            float4 o;
            o.x = f2tf32(qkv[base          ]);
            o.y = f2tf32(qkv[base +     str]);
            o.z = f2tf32(qkv[base + 2 * str]);
            o.w = f2tf32(qkv[base + 3 * str]);
            *(float4*)&vt[vd][m] = o;
        }
        __syncthreads();

        // ---- S = Q @ K^T : warp computes 32x64 ----
        float acc_s[2][8][4];
#pragma unroll
        for (int i = 0; i < 2; i++)
#pragma unroll
            for (int j = 0; j < 8; j++)
#pragma unroll
                for (int t = 0; t < 4; t++) acc_s[i][j][t] = 0.f;

#pragma unroll
        for (int kk = 0; kk < D_HEAD; kk += 8) {
            uint32_t aq[2][4];
#pragma unroll
            for (int mt = 0; mt < 2; mt++)
                ldsm_x4(aq[mt], &qs[sm0 + mt * 16 + (lane & 15)][kk + ((lane >> 4) << 2)]);
            uint32_t bk[4][4];
#pragma unroll
            for (int ntp = 0; ntp < 4; ntp++)
                ldsm_x4(bk[ntp], &ks[sc0 + ntp * 16 + ((lane >> 4) << 3) + (lane & 7)]
                                    [kk + (((lane >> 3) & 1) << 2)]);
#pragma unroll
            for (int nt = 0; nt < 8; nt++) {
                const uint32_t* bb = &bk[nt >> 1][(nt & 1) * 2];
#pragma unroll
                for (int mt = 0; mt < 2; mt++)
                    mma_tf32(acc_s[mt][nt], aq[mt], bb);
            }
        }

        // ---- f(s), stage P (tf32), row sums ----
#pragma unroll
        for (int mt = 0; mt < 2; mt++) {
            const int r1 = sm0 + mt * 16 + grp, r2 = r1 + 8;
            float rs1 = 0.f, rs2 = 0.f;
#pragma unroll
            for (int nt = 0; nt < 8; nt++) {
                float fx, fy, fz, fw, v;
                v = acc_s[mt][nt][0]; fx = fmaf(0.5f * v, v, 1.f + v);
                v = acc_s[mt][nt][1]; fy = fmaf(0.5f * v, v, 1.f + v);
                v = acc_s[mt][nt][2]; fz = fmaf(0.5f * v, v, 1.f + v);
                v = acc_s[mt][nt][3]; fw = fmaf(0.5f * v, v, 1.f + v);
                rs1 += fx + fy;
                rs2 += fz + fw;
                const int col = sc0 + nt * 8 + 2 * qd;
                *(float2*)&ps[r1][col] = make_float2(f2tf32(fx), f2tf32(fy));
                *(float2*)&ps[r2][col] = make_float2(f2tf32(fz), f2tf32(fw));
            }
            rs1 += __shfl_xor_sync(0xffffffffu, rs1, 1);
            rs1 += __shfl_xor_sync(0xffffffffu, rs1, 2);
            rs2 += __shfl_xor_sync(0xffffffffu, rs2, 1);
            rs2 += __shfl_xor_sync(0xffffffffu, rs2, 2);
            if (qd == 0) {
                atomicAdd(&denom[r1], rs1);
                atomicAdd(&denom[r2], rs2);
            }
        }
        __syncthreads();

        // ---- O += P @ V : warp computes 16x64, k = 128 ----
#pragma unroll
        for (int kk = 0; kk < KTILE; kk += 8) {
            uint32_t ap[4];
            ldsm_x4(ap, &ps[pm0 + (lane & 15)][kk + ((lane >> 4) << 2)]);
            uint32_t bv[4][4];
#pragma unroll
            for (int ntp = 0; ntp < 4; ntp++)
                ldsm_x4(bv[ntp], &vt[ntp * 16 + ((lane >> 4) << 3) + (lane & 7)]
                                    [kk + (((lane >> 3) & 1) << 2)]);
#pragma unroll
            for (int nt = 0; nt < 8; nt++) {
                const uint32_t* bb = &bv[nt >> 1][(nt & 1) * 2];
                mma_tf32(acc_o[nt], ap, bb);
            }
        }
    }
    __syncthreads();

    // ---- normalize + store ----
    const int r1 = pm0 + grp, r2 = r1 + 8;
    const float inv1 = 1.f / denom[r1];
    const float inv2 = 1.f / denom[r2];
#pragma unroll
    for (int nt = 0; nt < 8; nt++) {
        const int c = h * D_HEAD + nt * 8 + 2 * qd;
        const size_t base1 = (size_t)(b * N_TOK + row0 + r1) * C_DIM + c;
        const size_t base2 = (size_t)(b * N_TOK + row0 + r2) * C_DIM + c;
        *(float2*)&out[base1] = make_float2(acc_o[nt][0] * inv1, acc_o[nt][1] * inv1);
        *(float2*)&out[base2] = make_float2(acc_o[nt][2] * inv2, acc_o[nt][3] * inv2);
    }
}

// ============================================================
// launcher
// ============================================================
extern "C" void kernel_launch(void* const* d_in, const int* in_sizes, int n_in,
                              void* d_out, int out_size)
{
    const float* x      = (const float*)d_in[0];
    const float* w_qkv  = (const float*)d_in[1];
    const float* w_proj = (const float*)d_in[2];
    const float* b_proj = (const float*)d_in[3];
    float* out = (float*)d_out;

    float *qkv_s = nullptr, *attn_s = nullptr;
    cudaGetSymbolAddress((void**)&qkv_s, g_qkv);
    cudaGetSymbolAddress((void**)&attn_s, g_attn);
    cudaFuncSetAttribute(attn_tf32, cudaFuncAttributeMaxDynamicSharedMemorySize,
                         (int)ATTN_SMEM_BYTES);

    const int M = B_SZ * N_TOK;  // 8192

    // 1) qkv = x @ w_qkv      [8192,768] @ [768,2304]
    gemm_tf32<<<dim3((3 * C_DIM) / 128, M / 128), 256>>>(
        x, w_qkv, nullptr, qkv_s, M, 3 * C_DIM, C_DIM, 0);

    // 2) fused Taylor attention -> [B,N,C]
    attn_tf32<<<dim3(N_TOK / QROWS, B_SZ * H_NUM), 256, ATTN_SMEM_BYTES>>>(qkv_s, attn_s);

    // 3) out = attn @ w_proj + b_proj    [8192,768] @ [768,768]
    gemm_tf32<<<dim3(C_DIM / 128, M / 128), 256>>>(
        attn_s, w_proj, b_proj, out, M, C_DIM, C_DIM, 1);
}

// round 4
// speedup vs baseline: 4.0556x; 1.0498x over previous
#include <cuda_runtime.h>
#include <cstdint>
#include <cstddef>

// ---------------- problem constants ----------------
#define B_SZ   8
#define N_TOK  1024
#define C_DIM  768
#define H_NUM  12
#define D_HEAD 64
#define SCALE_Q 0.125f   // 64^-0.5

// ---------------- scratch (device globals; no cudaMalloc allowed) ----------------
__device__ float g_qkv [(size_t)B_SZ * N_TOK * 3 * C_DIM];   // tf32-rounded, Q pre-scaled
__device__ float g_attn[(size_t)B_SZ * N_TOK * C_DIM];       // tf32-rounded attention out
__device__ float g_xr  [(size_t)B_SZ * N_TOK * C_DIM];       // x, tf32-rounded
__device__ float g_wqkvT[(size_t)3 * C_DIM * C_DIM];         // w_qkv^T [2304][768], rounded
__device__ float g_wprojT[(size_t)C_DIM * C_DIM];            // w_proj^T [768][768], rounded

// ---------------- helpers ----------------
__device__ __forceinline__ float f2tf32(float x) {
    uint32_t u;
    asm("cvt.rna.tf32.f32 %0, %1;" : "=r"(u) : "f"(x));
    return __uint_as_float(u);
}

__device__ __forceinline__ void mma_tf32(float* d, const uint32_t* a, const uint32_t* b) {
    asm volatile(
        "mma.sync.aligned.m16n8k8.row.col.f32.tf32.tf32.f32 "
        "{%0,%1,%2,%3}, {%4,%5,%6,%7}, {%8,%9}, {%0,%1,%2,%3};"
        : "+f"(d[0]), "+f"(d[1]), "+f"(d[2]), "+f"(d[3])
        : "r"(a[0]), "r"(a[1]), "r"(a[2]), "r"(a[3]),
          "r"(b[0]), "r"(b[1]));
}

__device__ __forceinline__ void ldsm_x4(uint32_t* r, const float* p) {
    uint32_t addr = (uint32_t)__cvta_generic_to_shared(p);
    asm volatile(
        "ldmatrix.sync.aligned.m8n8.x4.shared.b16 {%0,%1,%2,%3}, [%4];"
        : "=r"(r[0]), "=r"(r[1]), "=r"(r[2]), "=r"(r[3]) : "r"(addr));
}

__device__ __forceinline__ void cp_async16(float* smem_dst, const float* gmem_src) {
    uint32_t a = (uint32_t)__cvta_generic_to_shared(smem_dst);
    asm volatile("cp.async.cg.shared.global [%0], [%1], 16;" :: "r"(a), "l"(gmem_src));
}
#define CP_COMMIT()  asm volatile("cp.async.commit_group;")
#define CP_WAIT(n)   asm volatile("cp.async.wait_group %0;" :: "n"(n))

// ============================================================
// pre-pass kernels
// ============================================================
__global__ __launch_bounds__(256) void round_tf32_kernel(
    const float* __restrict__ in, float* __restrict__ out, int n4)
{
    const int i = blockIdx.x * 256 + threadIdx.x;
    if (i >= n4) return;
    float4 v = ((const float4*)in)[i];
    v.x = f2tf32(v.x); v.y = f2tf32(v.y); v.z = f2tf32(v.z); v.w = f2tf32(v.w);
    ((float4*)out)[i] = v;
}

// in[R][Ncols] -> out[Ncols][R], tf32-rounded. block (32,8), grid (N/32, R/32)
__global__ __launch_bounds__(256) void transpose_round_kernel(
    const float* __restrict__ in, float* __restrict__ out, int R, int Ncols)
{
    __shared__ float tile[32][33];
    const int bx = blockIdx.x * 32, by = blockIdx.y * 32;
    const int tx = threadIdx.x, ty = threadIdx.y;
#pragma unroll
    for (int j = 0; j < 32; j += 8)
        tile[ty + j][tx] = in[(size_t)(by + ty + j) * Ncols + bx + tx];
    __syncthreads();
#pragma unroll
    for (int j = 0; j < 32; j += 8)
        out[(size_t)(bx + ty + j) * R + by + tx] = f2tf32(tile[tx][ty + j]);
}

// ============================================================
// TF32 GEMM: C[M,N] = A[M,K] @ BT[N,K]^T (+bias / +round&scale).
// A and BT already tf32-rounded. 128x128x16 tile, 4-stage cp.async,
// 8 warps (warp 64x32). round_mode=1: round output, scale cols<768.
// ============================================================
#define GT_PAD 20
#define STAGES 4
#define GEMM_SMEM_BYTES (STAGES * 2 * 128 * GT_PAD * 4)

__global__ __launch_bounds__(256, 2) void gemm_tf32(
    const float* __restrict__ A, const float* __restrict__ BT,
    const float* __restrict__ bias, float* __restrict__ C,
    int M, int N, int K, int has_bias, int round_mode)
{
    extern __shared__ float sm[];
    float (*As)[128][GT_PAD] = (float(*)[128][GT_PAD])(sm);
    float (*Bs)[128][GT_PAD] = (float(*)[128][GT_PAD])(sm + STAGES * 128 * GT_PAD);

    const int tid  = threadIdx.x;
    const int wid  = tid >> 5;
    const int lane = tid & 31;
    const int grp  = lane >> 2;
    const int qd   = lane & 3;

    const int brow = blockIdx.y * 128;
    const int bcol = blockIdx.x * 128;
    const int m_base = (wid & 1) * 64;
    const int n_base = (wid >> 1) * 32;

    // load mapping: idx = tid + l*256 -> r = idx>>2 (0..127), c4 = (idx&3)*4
    const int lr0 = tid >> 2;
    const int lc0 = (tid & 3) * 4;
    const int lr1 = (tid + 256) >> 2;
    const int lc1 = ((tid + 256) & 3) * 4;

    float acc[4][4][4];
#pragma unroll
    for (int i = 0; i < 4; i++)
#pragma unroll
        for (int j = 0; j < 4; j++)
#pragma unroll
            for (int t = 0; t < 4; t++) acc[i][j][t] = 0.f;

    auto load_tile = [&](int t, int s) {
        const int k0 = t * 16;
        cp_async16(&As[s][lr0][lc0], &A [(size_t)(brow + lr0) * K + k0 + lc0]);
        cp_async16(&As[s][lr1][lc1], &A [(size_t)(brow + lr1) * K + k0 + lc1]);
        cp_async16(&Bs[s][lr0][lc0], &BT[(size_t)(bcol + lr0) * K + k0 + lc0]);
        cp_async16(&Bs[s][lr1][lc1], &BT[(size_t)(bcol + lr1) * K + k0 + lc1]);
    };

    const int T = K / 16;
#pragma unroll
    for (int t = 0; t < STAGES - 1; t++) {
        if (t < T) load_tile(t, t);
        CP_COMMIT();
    }

    for (int t = 0; t < T; t++) {
        CP_WAIT(STAGES - 2);
        __syncthreads();
        const int buf = t & (STAGES - 1);
        if (t + STAGES - 1 < T) load_tile(t + STAGES - 1, (t + STAGES - 1) & (STAGES - 1));
        CP_COMMIT();

#pragma unroll
        for (int ks = 0; ks < 16; ks += 8) {
            uint32_t af[4][4];
#pragma unroll
            for (int mt = 0; mt < 4; mt++)
                ldsm_x4(af[mt], &As[buf][m_base + mt * 16 + (lane & 15)][ks + ((lane >> 4) << 2)]);
            uint32_t bf[2][4];
#pragma unroll
            for (int ntp = 0; ntp < 2; ntp++)
                ldsm_x4(bf[ntp], &Bs[buf][n_base + ntp * 16 + ((lane >> 4) << 3) + (lane & 7)]
                                         [ks + (((lane >> 3) & 1) << 2)]);
#pragma unroll
            for (int nt = 0; nt < 4; nt++) {
                const uint32_t* bb = &bf[nt >> 1][(nt & 1) * 2];
#pragma unroll
                for (int mt = 0; mt < 4; mt++)
                    mma_tf32(acc[mt][nt], af[mt], bb);
            }
        }
        __syncthreads();
    }

    // epilogue
#pragma unroll
    for (int mt = 0; mt < 4; mt++) {
        const int r1 = brow + m_base + mt * 16 + grp;
        const int r2 = r1 + 8;
#pragma unroll
        for (int nt = 0; nt < 4; nt++) {
            const int c = bcol + n_base + nt * 8 + 2 * qd;
            float v0 = acc[mt][nt][0], v1 = acc[mt][nt][1];
            float v2 = acc[mt][nt][2], v3 = acc[mt][nt][3];
            if (round_mode) {
                const float s = (c < C_DIM) ? SCALE_Q : 1.f;
                v0 = f2tf32(v0 * s); v1 = f2tf32(v1 * s);
                v2 = f2tf32(v2 * s); v3 = f2tf32(v3 * s);
            }
            if (has_bias) {
                const float b0 = __ldg(&bias[c]), b1 = __ldg(&bias[c + 1]);
                v0 += b0; v1 += b1; v2 += b0; v3 += b1;
            }
            *(float2*)&C[(size_t)r1 * N + c] = make_float2(v0, v1);
            *(float2*)&C[(size_t)r2 * N + c] = make_float2(v2, v3);
        }
    }
}

// ============================================================
// Fused Taylor attention, tf32 + ldmatrix + cp.async loads.
// qkv is pre-rounded (Q pre-scaled). Q tile 128 rows, K/V tile 128.
// grid = (8, 96), block = 256 (8 warps).
// ============================================================
#define QROWS 128
#define KTILE 128
#define APAD  68
#define VPAD  132

#define QS_OFF 0
#define KS_OFF (QS_OFF + QROWS * APAD)
#define VT_OFF (KS_OFF + KTILE * APAD)
#define PS_OFF (VT_OFF + D_HEAD * VPAD)
#define DN_OFF (PS_OFF + QROWS * VPAD)
#define ATTN_SMEM_FLOATS (DN_OFF + QROWS)
#define ATTN_SMEM_BYTES  (ATTN_SMEM_FLOATS * sizeof(float))

__global__ __launch_bounds__(256, 1) void attn_tf32(
    const float* __restrict__ qkv, float* __restrict__ out)
{
    extern __shared__ float smem[];
    float (*qs)[APAD] = (float(*)[APAD])(smem + QS_OFF);   // [qrow][d]
    float (*ks)[APAD] = (float(*)[APAD])(smem + KS_OFF);   // [krow][d]
    float (*vt)[VPAD] = (float(*)[VPAD])(smem + VT_OFF);   // [d][krow]
    float (*ps)[VPAD] = (float(*)[VPAD])(smem + PS_OFF);   // [qrow][krow]
    float* denom      = smem + DN_OFF;

    const int tid  = threadIdx.x;
    const int wid  = tid >> 5;
    const int lane = tid & 31;
    const int grp  = lane >> 2;
    const int qd   = lane & 3;

    const int b    = blockIdx.y / H_NUM;
    const int h    = blockIdx.y % H_NUM;
    const int row0 = blockIdx.x * QROWS;

    const int sm0 = (wid & 3) * 32;
    const int sc0 = (wid >> 2) * 64;
    const int pm0 = wid * 16;

    // tile load mapping: idx -> r = idx>>4, c4 = (idx&15)*4 (128x64 tile)
    // ---- Q tile via cp.async (already scaled+rounded) ----
#pragma unroll
    for (int l = 0; l < 8; l++) {
        const int idx = tid + l * 256;
        const int r = idx >> 4, c4 = (idx & 15) * 4;
        cp_async16(&qs[r][c4],
                   &qkv[((size_t)(b * N_TOK + row0 + r) * 3) * C_DIM + h * D_HEAD + c4]);
    }
    CP_COMMIT();
    if (tid < QROWS) denom[tid] = 0.f;

    float acc_o[8][4];
#pragma unroll
    for (int i = 0; i < 8; i++)
#pragma unroll
        for (int t = 0; t < 4; t++) acc_o[i][t] = 0.f;

    const int vd  = tid & 63;
    const int sel = tid >> 6;

    for (int m0 = 0; m0 < N_TOK; m0 += KTILE) {
        __syncthreads();   // protect ks/vt/ps reuse

        // ---- K tile via cp.async ----
#pragma unroll
        for (int l = 0; l < 8; l++) {
            const int idx = tid + l * 256;
            const int r = idx >> 4, c4 = (idx & 15) * 4;
            cp_async16(&ks[r][c4],
                       &qkv[((size_t)(b * N_TOK + m0 + r) * 3 + 1) * C_DIM + h * D_HEAD + c4]);
        }
        CP_COMMIT();

        // ---- V tile transposed: vt[d][m] (scalar LDG, float4 STS) ----
#pragma unroll
        for (int g = 0; g < 8; g++) {
            const int m = g * 16 + sel * 4;
            const size_t base = ((size_t)(b * N_TOK + m0 + m) * 3 + 2) * C_DIM + h * D_HEAD + vd;
            const size_t str  = (size_t)3 * C_DIM;
            float4 o;
            o.x = qkv[base          ];
            o.y = qkv[base +     str];
            o.z = qkv[base + 2 * str];
            o.w = qkv[base + 3 * str];
            *(float4*)&vt[vd][m] = o;
        }
        CP_WAIT(0);
        __syncthreads();

        // ---- S = Q @ K^T : warp computes 32x64 ----
        float acc_s[2][8][4];
#pragma unroll
        for (int i = 0; i < 2; i++)
#pragma unroll
            for (int j = 0; j < 8; j++)
#pragma unroll
                for (int t = 0; t < 4; t++) acc_s[i][j][t] = 0.f;

#pragma unroll
        for (int kk = 0; kk < D_HEAD; kk += 8) {
            uint32_t aq[2][4];
#pragma unroll
            for (int mt = 0; mt < 2; mt++)
                ldsm_x4(aq[mt], &qs[sm0 + mt * 16 + (lane & 15)][kk + ((lane >> 4) << 2)]);
            uint32_t bk[4][4];
#pragma unroll
            for (int ntp = 0; ntp < 4; ntp++)
                ldsm_x4(bk[ntp], &ks[sc0 + ntp * 16 + ((lane >> 4) << 3) + (lane & 7)]
                                    [kk + (((lane >> 3) & 1) << 2)]);
#pragma unroll
            for (int nt = 0; nt < 8; nt++) {
                const uint32_t* bb = &bk[nt >> 1][(nt & 1) * 2];
#pragma unroll
                for (int mt = 0; mt < 2; mt++)
                    mma_tf32(acc_s[mt][nt], aq[mt], bb);
            }
        }

        // ---- f(s) = 1 + s + s^2/2 (>0), stage P, row sums ----
#pragma unroll
        for (int mt = 0; mt < 2; mt++) {
            const int r1 = sm0 + mt * 16 + grp, r2 = r1 + 8;
            float rs1 = 0.f, rs2 = 0.f;
#pragma unroll
            for (int nt = 0; nt < 8; nt++) {
                float fx, fy, fz, fw, v;
                v = acc_s[mt][nt][0]; fx = fmaf(0.5f * v, v, 1.f + v);
                v = acc_s[mt][nt][1]; fy = fmaf(0.5f * v, v, 1.f + v);
                v = acc_s[mt][nt][2]; fz = fmaf(0.5f * v, v, 1.f + v);
                v = acc_s[mt][nt][3]; fw = fmaf(0.5f * v, v, 1.f + v);
                rs1 += fx + fy;
                rs2 += fz + fw;
                const int col = sc0 + nt * 8 + 2 * qd;
                *(float2*)&ps[r1][col] = make_float2(f2tf32(fx), f2tf32(fy));
                *(float2*)&ps[r2][col] = make_float2(f2tf32(fz), f2tf32(fw));
            }
            rs1 += __shfl_xor_sync(0xffffffffu, rs1, 1);
            rs1 += __shfl_xor_sync(0xffffffffu, rs1, 2);
            rs2 += __shfl_xor_sync(0xffffffffu, rs2, 1);
            rs2 += __shfl_xor_sync(0xffffffffu, rs2, 2);
            if (qd == 0) {
                atomicAdd(&denom[r1], rs1);
                atomicAdd(&denom[r2], rs2);
            }
        }
        __syncthreads();

        // ---- O += P @ V : warp computes 16x64, k = 128 ----
#pragma unroll
        for (int kk = 0; kk < KTILE; kk += 8) {
            uint32_t ap[4];
            ldsm_x4(ap, &ps[pm0 + (lane & 15)][kk + ((lane >> 4) << 2)]);
            uint32_t bv[4][4];
#pragma unroll
            for (int ntp = 0; ntp < 4; ntp++)
                ldsm_x4(bv[ntp], &vt[ntp * 16 + ((lane >> 4) << 3) + (lane & 7)]
                                    [kk + (((lane >> 3) & 1) << 2)]);
#pragma unroll
            for (int nt = 0; nt < 8; nt++) {
                const uint32_t* bb = &bv[nt >> 1][(nt & 1) * 2];
                mma_tf32(acc_o[nt], ap, bb);
            }
        }
    }
    __syncthreads();

    // ---- normalize + store (tf32-rounded for GEMM2's cp.async path) ----
    const int r1 = pm0 + grp, r2 = r1 + 8;
    const float inv1 = 1.f / denom[r1];
    const float inv2 = 1.f / denom[r2];
#pragma unroll
    for (int nt = 0; nt < 8; nt++) {
        const int c = h * D_HEAD + nt * 8 + 2 * qd;
        const size_t base1 = (size_t)(b * N_TOK + row0 + r1) * C_DIM + c;
        const size_t base2 = (size_t)(b * N_TOK + row0 + r2) * C_DIM + c;
        *(float2*)&out[base1] = make_float2(f2tf32(acc_o[nt][0] * inv1),
                                            f2tf32(acc_o[nt][1] * inv1));
        *(float2*)&out[base2] = make_float2(f2tf32(acc_o[nt][2] * inv2),
                                            f2tf32(acc_o[nt][3] * inv2));
    }
}

// ============================================================
// launcher
// ============================================================
extern "C" void kernel_launch(void* const* d_in, const int* in_sizes, int n_in,
                              void* d_out, int out_size)
{
    const float* x      = (const float*)d_in[0];
    const float* w_qkv  = (const float*)d_in[1];
    const float* w_proj = (const float*)d_in[2];
    const float* b_proj = (const float*)d_in[3];
    float* out = (float*)d_out;

    float *qkv_s, *attn_s, *xr_s, *wqkvT_s, *wprojT_s;
    cudaGetSymbolAddress((void**)&qkv_s,   g_qkv);
    cudaGetSymbolAddress((void**)&attn_s,  g_attn);
    cudaGetSymbolAddress((void**)&xr_s,    g_xr);
    cudaGetSymbolAddress((void**)&wqkvT_s, g_wqkvT);
    cudaGetSymbolAddress((void**)&wprojT_s, g_wprojT);

    cudaFuncSetAttribute(gemm_tf32, cudaFuncAttributeMaxDynamicSharedMemorySize,
                         (int)GEMM_SMEM_BYTES);
    cudaFuncSetAttribute(attn_tf32, cudaFuncAttributeMaxDynamicSharedMemorySize,
                         (int)ATTN_SMEM_BYTES);

    const int M = B_SZ * N_TOK;  // 8192

    // ---- pre-pass: round x; transpose+round weights ----
    {
        const int n4 = (M * C_DIM) / 4;
        round_tf32_kernel<<<(n4 + 255) / 256, 256>>>(x, xr_s, n4);
        transpose_round_kernel<<<dim3(3 * C_DIM / 32, C_DIM / 32), dim3(32, 8)>>>(
            w_qkv, wqkvT_s, C_DIM, 3 * C_DIM);
        transpose_round_kernel<<<dim3(C_DIM / 32, C_DIM / 32), dim3(32, 8)>>>(
            w_proj, wprojT_s, C_DIM, C_DIM);
    }

    // 1) qkv = x @ w_qkv  (output tf32-rounded, Q cols pre-scaled)
    gemm_tf32<<<dim3((3 * C_DIM) / 128, M / 128), 256, GEMM_SMEM_BYTES>>>(
        xr_s, wqkvT_s, nullptr, qkv_s, M, 3 * C_DIM, C_DIM, 0, 1);

    // 2) fused Taylor attention
    attn_tf32<<<dim3(N_TOK / QROWS, B_SZ * H_NUM), 256, ATTN_SMEM_BYTES>>>(qkv_s, attn_s);

    // 3) out = attn @ w_proj + b_proj
    gemm_tf32<<<dim3(C_DIM / 128, M / 128), 256, GEMM_SMEM_BYTES>>>(
        attn_s, wprojT_s, b_proj, out, M, C_DIM, C_DIM, 1, 0);
}

// round 6
// speedup vs baseline: 7.2154x; 1.7791x over previous
#include <cuda_runtime.h>
#include <cuda_fp16.h>
#include <cstdint>
#include <cstddef>

// ---------------- problem constants ----------------
#define B_SZ   8
#define N_TOK  1024
#define C_DIM  768
#define H_NUM  12
#define D_HEAD 64
#define SCALE_Q 0.125f   // 64^-0.5

// ---------------- scratch (device globals; no cudaMalloc allowed) ----------------
__device__ __half g_qkv [(size_t)B_SZ * N_TOK * 3 * C_DIM];   // fp16, Q pre-scaled
__device__ __half g_attn[(size_t)B_SZ * N_TOK * C_DIM];       // fp16 attention out
__device__ __half g_xh  [(size_t)B_SZ * N_TOK * C_DIM];       // x -> fp16
__device__ __half g_wqkvT[(size_t)3 * C_DIM * C_DIM];         // w_qkv^T [2304][768] fp16
__device__ __half g_wprojT[(size_t)C_DIM * C_DIM];            // w_proj^T [768][768] fp16

// ---------------- helpers ----------------
__device__ __forceinline__ void mma_f16(float* d, const uint32_t* a, const uint32_t* b) {
    asm volatile(
        "mma.sync.aligned.m16n8k16.row.col.f32.f16.f16.f32 "
        "{%0,%1,%2,%3}, {%4,%5,%6,%7}, {%8,%9}, {%0,%1,%2,%3};"
        : "+f"(d[0]), "+f"(d[1]), "+f"(d[2]), "+f"(d[3])
        : "r"(a[0]), "r"(a[1]), "r"(a[2]), "r"(a[3]),
          "r"(b[0]), "r"(b[1]));
}

__device__ __forceinline__ void ldsm_x4(uint32_t* r, const __half* p) {
    uint32_t addr = (uint32_t)__cvta_generic_to_shared(p);
    asm volatile(
        "ldmatrix.sync.aligned.m8n8.x4.shared.b16 {%0,%1,%2,%3}, [%4];"
        : "=r"(r[0]), "=r"(r[1]), "=r"(r[2]), "=r"(r[3]) : "r"(addr));
}

__device__ __forceinline__ void ldsm_x4_trans(uint32_t* r, const __half* p) {
    uint32_t addr = (uint32_t)__cvta_generic_to_shared(p);
    asm volatile(
        "ldmatrix.sync.aligned.m8n8.x4.trans.shared.b16 {%0,%1,%2,%3}, [%4];"
        : "=r"(r[0]), "=r"(r[1]), "=r"(r[2]), "=r"(r[3]) : "r"(addr));
}

__device__ __forceinline__ void cp_async16(void* smem_dst, const void* gmem_src) {
    uint32_t a = (uint32_t)__cvta_generic_to_shared(smem_dst);
    asm volatile("cp.async.cg.shared.global [%0], [%1], 16;" :: "r"(a), "l"(gmem_src));
}
#define CP_COMMIT()  asm volatile("cp.async.commit_group;")
#define CP_WAIT(n)   asm volatile("cp.async.wait_group %0;" :: "n"(n))

// ============================================================
// pre-pass kernels
// ============================================================
__global__ __launch_bounds__(256) void to_half_kernel(
    const float* __restrict__ in, __half* __restrict__ out, int n4)
{
    const int i = blockIdx.x * 256 + threadIdx.x;
    if (i >= n4) return;
    float4 v = ((const float4*)in)[i];
    __half2* o = (__half2*)(out + (size_t)i * 4);
    o[0] = __floats2half2_rn(v.x, v.y);
    o[1] = __floats2half2_rn(v.z, v.w);
}

// in[R][Ncols] fp32 -> out[Ncols][R] fp16
__global__ __launch_bounds__(256) void transpose_half_kernel(
    const float* __restrict__ in, __half* __restrict__ out, int R, int Ncols)
{
    __shared__ float tile[32][33];
    const int bx = blockIdx.x * 32, by = blockIdx.y * 32;
    const int tx = threadIdx.x, ty = threadIdx.y;
#pragma unroll
    for (int j = 0; j < 32; j += 8)
        tile[ty + j][tx] = in[(size_t)(by + ty + j) * Ncols + bx + tx];
    __syncthreads();
#pragma unroll
    for (int j = 0; j < 32; j += 8)
        out[(size_t)(bx + ty + j) * R + by + tx] = __float2half_rn(tile[tx][ty + j]);
}

// ============================================================
// FP16 GEMM: C[M,N] = A[M,K] @ BT[N,K]^T. 128x128x32 tile,
// 4-stage cp.async, 8 warps (warp 64x32), m16n8k16.
// out_mode 0: fp32 out (+bias). 1: fp16 out, scale cols<768 by SCALE_Q.
// ============================================================
#define GPITCH 40   // 32 + 8 halves -> 80B pitch (odd multiple of 16B)
#define STAGES 4
#define GEMM_SMEM_BYTES (STAGES * 2 * 128 * GPITCH * 2)   // 81920

__global__ __launch_bounds__(256, 2) void gemm_f16(
    const __half* __restrict__ A, const __half* __restrict__ BT,
    const float* __restrict__ bias, void* __restrict__ Cout,
    int M, int N, int K, int has_bias, int out_half)
{
    extern __shared__ __half smh[];
    __half (*As)[128][GPITCH] = (__half(*)[128][GPITCH])(smh);
    __half (*Bs)[128][GPITCH] = (__half(*)[128][GPITCH])(smh + STAGES * 128 * GPITCH);

    const int tid  = threadIdx.x;
    const int wid  = tid >> 5;
    const int lane = tid & 31;
    const int grp  = lane >> 2;
    const int qd   = lane & 3;

    const int brow = blockIdx.y * 128;
    const int bcol = blockIdx.x * 128;
    const int m_base = (wid & 1) * 64;
    const int n_base = (wid >> 1) * 32;

    float acc[4][4][4];
#pragma unroll
    for (int i = 0; i < 4; i++)
#pragma unroll
        for (int j = 0; j < 4; j++)
#pragma unroll
            for (int t = 0; t < 4; t++) acc[i][j][t] = 0.f;

    // tile = 128 rows x 32 halves = 512 16B-chunks per operand; 2 per thread
    auto load_tile = [&](int t, int s) {
        const int k0 = t * 32;
#pragma unroll
        for (int i = 0; i < 2; i++) {
            const int ch = tid + i * 256;
            const int r = ch >> 2, co = (ch & 3) * 8;
            cp_async16(&As[s][r][co], &A [(size_t)(brow + r) * K + k0 + co]);
            cp_async16(&Bs[s][r][co], &BT[(size_t)(bcol + r) * K + k0 + co]);
        }
    };

    const int T = K / 32;
#pragma unroll
    for (int t = 0; t < STAGES - 1; t++) {
        if (t < T) load_tile(t, t);
        CP_COMMIT();
    }

    for (int t = 0; t < T; t++) {
        CP_WAIT(STAGES - 2);
        __syncthreads();
        const int buf = t & (STAGES - 1);
        if (t + STAGES - 1 < T) load_tile(t + STAGES - 1, (t + STAGES - 1) & (STAGES - 1));
        CP_COMMIT();

#pragma unroll
        for (int ks = 0; ks < 32; ks += 16) {
            uint32_t af[4][4];
#pragma unroll
            for (int mt = 0; mt < 4; mt++)
                ldsm_x4(af[mt], &As[buf][m_base + mt * 16 + (lane & 15)][ks + ((lane >> 4) << 3)]);
            uint32_t bf[2][4];
#pragma unroll
            for (int ntp = 0; ntp < 2; ntp++)
                ldsm_x4(bf[ntp], &Bs[buf][n_base + ntp * 16 + ((lane >> 4) << 3) + (lane & 7)]
                                         [ks + (((lane >> 3) & 1) << 3)]);
#pragma unroll
            for (int nt = 0; nt < 4; nt++) {
                const uint32_t* bb = &bf[nt >> 1][(nt & 1) * 2];
#pragma unroll
                for (int mt = 0; mt < 4; mt++)
                    mma_f16(acc[mt][nt], af[mt], bb);
            }
        }
        __syncthreads();
    }

    // epilogue
#pragma unroll
    for (int mt = 0; mt < 4; mt++) {
        const int r1 = brow + m_base + mt * 16 + grp;
        const int r2 = r1 + 8;
#pragma unroll
        for (int nt = 0; nt < 4; nt++) {
            const int c = bcol + n_base + nt * 8 + 2 * qd;
            float v0 = acc[mt][nt][0], v1 = acc[mt][nt][1];
            float v2 = acc[mt][nt][2], v3 = acc[mt][nt][3];
            if (out_half) {
                const float s = (c < C_DIM) ? SCALE_Q : 1.f;
                __half* Ch = (__half*)Cout;
                *(__half2*)&Ch[(size_t)r1 * N + c] = __floats2half2_rn(v0 * s, v1 * s);
                *(__half2*)&Ch[(size_t)r2 * N + c] = __floats2half2_rn(v2 * s, v3 * s);
            } else {
                float b0 = 0.f, b1 = 0.f;
                if (has_bias) { b0 = __ldg(&bias[c]); b1 = __ldg(&bias[c + 1]); }
                float* Cf = (float*)Cout;
                *(float2*)&Cf[(size_t)r1 * N + c] = make_float2(v0 + b0, v1 + b1);
                *(float2*)&Cf[(size_t)r2 * N + c] = make_float2(v2 + b0, v3 + b1);
            }
        }
    }
}

// ============================================================
// Fused Taylor attention, fp16 m16n8k16. Q tile 128, K/V tile 128.
// grid = (8, 96), block = 256 (8 warps).
// S phase: warp -> 32x64 of S; PV phase: warp -> 16x64 of O.
// V loaded row-major [m][d]; PV B-fragments via ldmatrix.trans.
// f(s) = 1 + s + s^2/2 > 0 (relu no-op).
// ============================================================
#define QROWS 128
#define KTILE 128
#define HPITCH 72    // 64+8 halves = 144B pitch
#define PPITCH 136   // 128+8 halves = 272B pitch

#define QS_OFF 0
#define KS_OFF (QS_OFF + QROWS * HPITCH)
#define VS_OFF (KS_OFF + KTILE * HPITCH)
#define PS_OFF (VS_OFF + KTILE * HPITCH)
#define DN_OFF (PS_OFF + QROWS * PPITCH)            // halves; denom is float[]
#define ATTN_SMEM_BYTES (DN_OFF * 2 + QROWS * 4)

__global__ __launch_bounds__(256, 1) void attn_f16(
    const __half* __restrict__ qkv, __half* __restrict__ out)
{
    extern __shared__ __half smh[];
    __half (*qs)[HPITCH] = (__half(*)[HPITCH])(smh + QS_OFF);
    __half (*ks)[HPITCH] = (__half(*)[HPITCH])(smh + KS_OFF);
    __half (*vs)[HPITCH] = (__half(*)[HPITCH])(smh + VS_OFF);   // [m][d]
    __half (*ps)[PPITCH] = (__half(*)[PPITCH])(smh + PS_OFF);
    float* denom         = (float*)(smh + DN_OFF);

    const int tid  = threadIdx.x;
    const int wid  = tid >> 5;
    const int lane = tid & 31;
    const int grp  = lane >> 2;
    const int qd   = lane & 3;

    const int b    = blockIdx.y / H_NUM;
    const int h    = blockIdx.y % H_NUM;
    const int row0 = blockIdx.x * QROWS;

    const int sm0 = (wid & 3) * 32;    // S-phase rows
    const int sc0 = (wid >> 2) * 64;   // S-phase cols
    const int pm0 = wid * 16;          // PV-phase rows

    // ---- Q tile: 128x64 halves = 1024 chunks, 4/thread ----
#pragma unroll
    for (int l = 0; l < 4; l++) {
        const int ch = tid + l * 256;
        const int r = ch >> 3, co = (ch & 7) * 8;
        cp_async16(&qs[r][co],
                   &qkv[((size_t)(b * N_TOK + row0 + r) * 3) * C_DIM + h * D_HEAD + co]);
    }
    CP_COMMIT();
    if (tid < QROWS) denom[tid] = 0.f;

    float acc_o[8][4];
#pragma unroll
    for (int i = 0; i < 8; i++)
#pragma unroll
        for (int t = 0; t < 4; t++) acc_o[i][t] = 0.f;

    for (int m0 = 0; m0 < N_TOK; m0 += KTILE) {
        __syncthreads();   // protect ks/vs/ps reuse

        // ---- K and V tiles via cp.async ----
#pragma unroll
        for (int l = 0; l < 4; l++) {
            const int ch = tid + l * 256;
            const int r = ch >> 3, co = (ch & 7) * 8;
            const size_t nb = (size_t)(b * N_TOK + m0 + r) * 3;
            cp_async16(&ks[r][co], &qkv[(nb + 1) * C_DIM + h * D_HEAD + co]);
            cp_async16(&vs[r][co], &qkv[(nb + 2) * C_DIM + h * D_HEAD + co]);
        }
        CP_COMMIT();
        CP_WAIT(0);
        __syncthreads();

        // ---- S = Q @ K^T : warp computes 32x64, k=64 (4 steps) ----
        float acc_s[2][8][4];
#pragma unroll
        for (int i = 0; i < 2; i++)
#pragma unroll
            for (int j = 0; j < 8; j++)
#pragma unroll
                for (int t = 0; t < 4; t++) acc_s[i][j][t] = 0.f;

#pragma unroll
        for (int kk = 0; kk < D_HEAD; kk += 16) {
            uint32_t aq[2][4];
#pragma unroll
            for (int mt = 0; mt < 2; mt++)
                ldsm_x4(aq[mt], &qs[sm0 + mt * 16 + (lane & 15)][kk + ((lane >> 4) << 3)]);
            uint32_t bk[4][4];
#pragma unroll
            for (int ntp = 0; ntp < 4; ntp++)
                ldsm_x4(bk[ntp], &ks[sc0 + ntp * 16 + ((lane >> 4) << 3) + (lane & 7)]
                                    [kk + (((lane >> 3) & 1) << 3)]);
#pragma unroll
            for (int nt = 0; nt < 8; nt++) {
                const uint32_t* bb = &bk[nt >> 1][(nt & 1) * 2];
#pragma unroll
                for (int mt = 0; mt < 2; mt++)
                    mma_f16(acc_s[mt][nt], aq[mt], bb);
            }
        }

        // ---- f(s), stage P (fp16), row sums ----
#pragma unroll
        for (int mt = 0; mt < 2; mt++) {
            const int r1 = sm0 + mt * 16 + grp, r2 = r1 + 8;
            float rs1 = 0.f, rs2 = 0.f;
#pragma unroll
            for (int nt = 0; nt < 8; nt++) {
                float fx, fy, fz, fw, v;
                v = acc_s[mt][nt][0]; fx = fmaf(0.5f * v, v, 1.f + v);
                v = acc_s[mt][nt][1]; fy = fmaf(0.5f * v, v, 1.f + v);
                v = acc_s[mt][nt][2]; fz = fmaf(0.5f * v, v, 1.f + v);
                v = acc_s[mt][nt][3]; fw = fmaf(0.5f * v, v, 1.f + v);
                rs1 += fx + fy;
                rs2 += fz + fw;
                const int col = sc0 + nt * 8 + 2 * qd;
                *(__half2*)&ps[r1][col] = __floats2half2_rn(fx, fy);
                *(__half2*)&ps[r2][col] = __floats2half2_rn(fz, fw);
            }
            rs1 += __shfl_xor_sync(0xffffffffu, rs1, 1);
            rs1 += __shfl_xor_sync(0xffffffffu, rs1, 2);
            rs2 += __shfl_xor_sync(0xffffffffu, rs2, 1);
            rs2 += __shfl_xor_sync(0xffffffffu, rs2, 2);
            if (qd == 0) {
                atomicAdd(&denom[r1], rs1);
                atomicAdd(&denom[r2], rs2);
            }
        }
        __syncthreads();

        // ---- O += P @ V : warp 16x64, k=128 (8 steps); V via ldsm.trans ----
#pragma unroll
        for (int kk = 0; kk < KTILE; kk += 16) {
            uint32_t ap[4];
            ldsm_x4(ap, &ps[pm0 + (lane & 15)][kk + ((lane >> 4) << 3)]);
            uint32_t bv[4][4];
#pragma unroll
            for (int dp = 0; dp < 4; dp++)   // d-groups 2dp, 2dp+1
                ldsm_x4_trans(bv[dp],
                    &vs[kk + (((lane >> 3) & 1) << 3) + (lane & 7)]
                       [dp * 16 + ((lane >> 4) << 3)]);
#pragma unroll
            for (int nt = 0; nt < 8; nt++) {
                const uint32_t* bb = &bv[nt >> 1][(nt & 1) * 2];
                mma_f16(acc_o[nt], ap, bb);
            }
        }
    }
    __syncthreads();

    // ---- normalize + store fp16 ----
    const int r1 = pm0 + grp, r2 = r1 + 8;
    const float inv1 = 1.f / denom[r1];
    const float inv2 = 1.f / denom[r2];
#pragma unroll
    for (int nt = 0; nt < 8; nt++) {
        const int c = h * D_HEAD + nt * 8 + 2 * qd;
        const size_t base1 = (size_t)(b * N_TOK + row0 + r1) * C_DIM + c;
        const size_t base2 = (size_t)(b * N_TOK + row0 + r2) * C_DIM + c;
        *(__half2*)&out[base1] = __floats2half2_rn(acc_o[nt][0] * inv1, acc_o[nt][1] * inv1);
        *(__half2*)&out[base2] = __floats2half2_rn(acc_o[nt][2] * inv2, acc_o[nt][3] * inv2);
    }
}

// ============================================================
// launcher
// ============================================================
extern "C" void kernel_launch(void* const* d_in, const int* in_sizes, int n_in,
                              void* d_out, int out_size)
{
    const float* x      = (const float*)d_in[0];
    const float* w_qkv  = (const float*)d_in[1];
    const float* w_proj = (const float*)d_in[2];
    const float* b_proj = (const float*)d_in[3];
    float* out = (float*)d_out;

    __half *qkv_s, *attn_s, *xh_s, *wqkvT_s, *wprojT_s;
    cudaGetSymbolAddress((void**)&qkv_s,    g_qkv);
    cudaGetSymbolAddress((void**)&attn_s,   g_attn);
    cudaGetSymbolAddress((void**)&xh_s,     g_xh);
    cudaGetSymbolAddress((void**)&wqkvT_s,  g_wqkvT);
    cudaGetSymbolAddress((void**)&wprojT_s, g_wprojT);

    cudaFuncSetAttribute(gemm_f16, cudaFuncAttributeMaxDynamicSharedMemorySize,
                         (int)GEMM_SMEM_BYTES);
    cudaFuncSetAttribute(attn_f16, cudaFuncAttributeMaxDynamicSharedMemorySize,
                         (int)ATTN_SMEM_BYTES);

    const int M = B_SZ * N_TOK;  // 8192

    // ---- pre-pass: x -> fp16; transpose weights -> fp16 ----
    {
        const int n4 = (M * C_DIM) / 4;
        to_half_kernel<<<(n4 + 255) / 256, 256>>>(x, xh_s, n4);
        transpose_half_kernel<<<dim3(3 * C_DIM / 32, C_DIM / 32), dim3(32, 8)>>>(
            w_qkv, wqkvT_s, C_DIM, 3 * C_DIM);
        transpose_half_kernel<<<dim3(C_DIM / 32, C_DIM / 32), dim3(32, 8)>>>(
            w_proj, wprojT_s, C_DIM, C_DIM);
    }

    // 1) qkv = x @ w_qkv  (fp16 out, Q cols pre-scaled)
    gemm_f16<<<dim3(3 * C_DIM / 128, M / 128), 256, GEMM_SMEM_BYTES>>>(
        xh_s, wqkvT_s, nullptr, qkv_s, M, 3 * C_DIM, C_DIM, 0, 1);

    // 2) fused Taylor attention -> fp16
    attn_f16<<<dim3(N_TOK / QROWS, B_SZ * H_NUM), 256, ATTN_SMEM_BYTES>>>(qkv_s, attn_s);

    // 3) out = attn @ w_proj + b_proj  (fp32 out)
    gemm_f16<<<dim3(C_DIM / 128, M / 128), 256, GEMM_SMEM_BYTES>>>(
        attn_s, wprojT_s, b_proj, out, M, C_DIM, C_DIM, 1, 0);
}

// round 7
// speedup vs baseline: 7.5440x; 1.0455x over previous
#include <cuda_runtime.h>
#include <cuda_fp16.h>
#include <cstdint>
#include <cstddef>

// ---------------- problem constants ----------------
#define B_SZ   8
#define N_TOK  1024
#define C_DIM  768
#define H_NUM  12
#define D_HEAD 64
#define SCALE_Q 0.125f   // 64^-0.5

// ---------------- scratch (device globals; no cudaMalloc allowed) ----------------
__device__ __half g_qkv [(size_t)B_SZ * N_TOK * 3 * C_DIM];   // fp16, Q pre-scaled
__device__ __half g_attn[(size_t)B_SZ * N_TOK * C_DIM];       // fp16 attention out
__device__ __half g_xh  [(size_t)B_SZ * N_TOK * C_DIM];       // x -> fp16
__device__ __half g_wqkvT[(size_t)3 * C_DIM * C_DIM];         // w_qkv^T [2304][768] fp16
__device__ __half g_wprojT[(size_t)C_DIM * C_DIM];            // w_proj^T [768][768] fp16

// ---------------- helpers ----------------
__device__ __forceinline__ void mma_f16(float* d, const uint32_t* a, const uint32_t* b) {
    asm volatile(
        "mma.sync.aligned.m16n8k16.row.col.f32.f16.f16.f32 "
        "{%0,%1,%2,%3}, {%4,%5,%6,%7}, {%8,%9}, {%0,%1,%2,%3};"
        : "+f"(d[0]), "+f"(d[1]), "+f"(d[2]), "+f"(d[3])
        : "r"(a[0]), "r"(a[1]), "r"(a[2]), "r"(a[3]),
          "r"(b[0]), "r"(b[1]));
}

__device__ __forceinline__ void ldsm_x4(uint32_t* r, const __half* p) {
    uint32_t addr = (uint32_t)__cvta_generic_to_shared(p);
    asm volatile(
        "ldmatrix.sync.aligned.m8n8.x4.shared.b16 {%0,%1,%2,%3}, [%4];"
        : "=r"(r[0]), "=r"(r[1]), "=r"(r[2]), "=r"(r[3]) : "r"(addr));
}

__device__ __forceinline__ void ldsm_x4_trans(uint32_t* r, const __half* p) {
    uint32_t addr = (uint32_t)__cvta_generic_to_shared(p);
    asm volatile(
        "ldmatrix.sync.aligned.m8n8.x4.trans.shared.b16 {%0,%1,%2,%3}, [%4];"
        : "=r"(r[0]), "=r"(r[1]), "=r"(r[2]), "=r"(r[3]) : "r"(addr));
}

__device__ __forceinline__ void cp_async16(void* smem_dst, const void* gmem_src) {
    uint32_t a = (uint32_t)__cvta_generic_to_shared(smem_dst);
    asm volatile("cp.async.cg.shared.global [%0], [%1], 16;" :: "r"(a), "l"(gmem_src));
}
#define CP_COMMIT()  asm volatile("cp.async.commit_group;")
#define CP_WAIT(n)   asm volatile("cp.async.wait_group %0;" :: "n"(n))

// ============================================================
// pre-pass kernels
// ============================================================
__global__ __launch_bounds__(256) void to_half_kernel(
    const float* __restrict__ in, __half* __restrict__ out, int n4)
{
    const int i = blockIdx.x * 256 + threadIdx.x;
    if (i >= n4) return;
    float4 v = ((const float4*)in)[i];
    __half2* o = (__half2*)(out + (size_t)i * 4);
    o[0] = __floats2half2_rn(v.x, v.y);
    o[1] = __floats2half2_rn(v.z, v.w);
}

__global__ __launch_bounds__(256) void transpose_half_kernel(
    const float* __restrict__ in, __half* __restrict__ out, int R, int Ncols)
{
    __shared__ float tile[32][33];
    const int bx = blockIdx.x * 32, by = blockIdx.y * 32;
    const int tx = threadIdx.x, ty = threadIdx.y;
#pragma unroll
    for (int j = 0; j < 32; j += 8)
        tile[ty + j][tx] = in[(size_t)(by + ty + j) * Ncols + bx + tx];
    __syncthreads();
#pragma unroll
    for (int j = 0; j < 32; j += 8)
        out[(size_t)(bx + ty + j) * R + by + tx] = __float2half_rn(tile[tx][ty + j]);
}

// ============================================================
// FP16 GEMM: C[M,N] = A[M,K] @ BT[N,K]^T. 128x128x32 tile,
// 5-stage cp.async ring, ONE barrier per k-tile, m16n8k16.
// ============================================================
#define GPITCH 40   // 32 + 8 halves -> 80B pitch
#define STAGES 5
#define GEMM_SMEM_BYTES (STAGES * 2 * 128 * GPITCH * 2)   // 102400

__global__ __launch_bounds__(256, 2) void gemm_f16(
    const __half* __restrict__ A, const __half* __restrict__ BT,
    const float* __restrict__ bias, void* __restrict__ Cout,
    int M, int N, int K, int has_bias, int out_half)
{
    extern __shared__ __half smh[];
    __half (*As)[128][GPITCH] = (__half(*)[128][GPITCH])(smh);
    __half (*Bs)[128][GPITCH] = (__half(*)[128][GPITCH])(smh + STAGES * 128 * GPITCH);

    const int tid  = threadIdx.x;
    const int wid  = tid >> 5;
    const int lane = tid & 31;
    const int grp  = lane >> 2;
    const int qd   = lane & 3;

    const int brow = blockIdx.y * 128;
    const int bcol = blockIdx.x * 128;
    const int m_base = (wid & 1) * 64;
    const int n_base = (wid >> 1) * 32;

    float acc[4][4][4];
#pragma unroll
    for (int i = 0; i < 4; i++)
#pragma unroll
        for (int j = 0; j < 4; j++)
#pragma unroll
            for (int t = 0; t < 4; t++) acc[i][j][t] = 0.f;

    auto load_tile = [&](int t, int s) {
        const int k0 = t * 32;
#pragma unroll
        for (int i = 0; i < 2; i++) {
            const int ch = tid + i * 256;
            const int r = ch >> 2, co = (ch & 3) * 8;
            cp_async16(&As[s][r][co], &A [(size_t)(brow + r) * K + k0 + co]);
            cp_async16(&Bs[s][r][co], &BT[(size_t)(bcol + r) * K + k0 + co]);
        }
    };

    const int T = K / 32;
#pragma unroll
    for (int t = 0; t < STAGES - 1; t++) {
        if (t < T) load_tile(t, t);
        CP_COMMIT();
    }

    int buf = 0, lbuf = (STAGES - 1) % STAGES;
    for (int t = 0; t < T; t++) {
        CP_WAIT(STAGES - 2);       // tile t resident
        __syncthreads();           // orders prior compute + makes loads visible
        if (t + STAGES - 1 < T) load_tile(t + STAGES - 1, lbuf);
        CP_COMMIT();

#pragma unroll
        for (int ks = 0; ks < 32; ks += 16) {
            uint32_t af[4][4];
#pragma unroll
            for (int mt = 0; mt < 4; mt++)
                ldsm_x4(af[mt], &As[buf][m_base + mt * 16 + (lane & 15)][ks + ((lane >> 4) << 3)]);
            uint32_t bf[2][4];
#pragma unroll
            for (int ntp = 0; ntp < 2; ntp++)
                ldsm_x4(bf[ntp], &Bs[buf][n_base + ntp * 16 + ((lane >> 4) << 3) + (lane & 7)]
                                         [ks + (((lane >> 3) & 1) << 3)]);
#pragma unroll
            for (int nt = 0; nt < 4; nt++) {
                const uint32_t* bb = &bf[nt >> 1][(nt & 1) * 2];
#pragma unroll
                for (int mt = 0; mt < 4; mt++)
                    mma_f16(acc[mt][nt], af[mt], bb);
            }
        }
        if (++buf == STAGES) buf = 0;
        if (++lbuf == STAGES) lbuf = 0;
    }

    // epilogue
#pragma unroll
    for (int mt = 0; mt < 4; mt++) {
        const int r1 = brow + m_base + mt * 16 + grp;
        const int r2 = r1 + 8;
#pragma unroll
        for (int nt = 0; nt < 4; nt++) {
            const int c = bcol + n_base + nt * 8 + 2 * qd;
            float v0 = acc[mt][nt][0], v1 = acc[mt][nt][1];
            float v2 = acc[mt][nt][2], v3 = acc[mt][nt][3];
            if (out_half) {
                const float s = (c < C_DIM) ? SCALE_Q : 1.f;
                __half* Ch = (__half*)Cout;
                *(__half2*)&Ch[(size_t)r1 * N + c] = __floats2half2_rn(v0 * s, v1 * s);
                *(__half2*)&Ch[(size_t)r2 * N + c] = __floats2half2_rn(v2 * s, v3 * s);
            } else {
                float b0 = 0.f, b1 = 0.f;
                if (has_bias) { b0 = __ldg(&bias[c]); b1 = __ldg(&bias[c + 1]); }
                float* Cf = (float*)Cout;
                *(float2*)&Cf[(size_t)r1 * N + c] = make_float2(v0 + b0, v1 + b1);
                *(float2*)&Cf[(size_t)r2 * N + c] = make_float2(v2 + b0, v3 + b1);
            }
        }
    }
}

// ============================================================
// Fused Taylor attention, fp16 m16n8k16, DOUBLE-BUFFERED K/V.
// Q tile 128, K/V tile 128. grid = (8, 96), block = 256 (8 warps).
// KV(t+1) cp.async overlaps the whole S/P/PV compute of tile t.
// ============================================================
#define QROWS 128
#define KTILE 128
#define HPITCH 72    // 64+8 halves = 144B pitch
#define PPITCH 136   // 128+8 halves = 272B pitch

#define QS_OFF 0
#define KS_OFF (QS_OFF + QROWS * HPITCH)
#define VS_OFF (KS_OFF + 2 * KTILE * HPITCH)
#define PS_OFF (VS_OFF + 2 * KTILE * HPITCH)
#define DN_OFF (PS_OFF + QROWS * PPITCH)            // halves; denom is float[]
#define ATTN_SMEM_BYTES (DN_OFF * 2 + QROWS * 4)

__global__ __launch_bounds__(256, 1) void attn_f16(
    const __half* __restrict__ qkv, __half* __restrict__ out)
{
    extern __shared__ __half smh[];
    __half (*qs)[HPITCH] = (__half(*)[HPITCH])(smh + QS_OFF);
    __half (*ks)[KTILE][HPITCH] = (__half(*)[KTILE][HPITCH])(smh + KS_OFF);
    __half (*vs)[KTILE][HPITCH] = (__half(*)[KTILE][HPITCH])(smh + VS_OFF);
    __half (*ps)[PPITCH] = (__half(*)[PPITCH])(smh + PS_OFF);
    float* denom         = (float*)(smh + DN_OFF);

    const int tid  = threadIdx.x;
    const int wid  = tid >> 5;
    const int lane = tid & 31;
    const int grp  = lane >> 2;
    const int qd   = lane & 3;

    const int b    = blockIdx.y / H_NUM;
    const int h    = blockIdx.y % H_NUM;
    const int row0 = blockIdx.x * QROWS;

    const int sm0 = (wid & 3) * 32;    // S-phase rows
    const int sc0 = (wid >> 2) * 64;   // S-phase cols
    const int pm0 = wid * 16;          // PV-phase rows

    auto load_kv = [&](int m0, int s) {
#pragma unroll
        for (int l = 0; l < 4; l++) {
            const int ch = tid + l * 256;
            const int r = ch >> 3, co = (ch & 7) * 8;
            const size_t nb = (size_t)(b * N_TOK + m0 + r) * 3;
            cp_async16(&ks[s][r][co], &qkv[(nb + 1) * C_DIM + h * D_HEAD + co]);
            cp_async16(&vs[s][r][co], &qkv[(nb + 2) * C_DIM + h * D_HEAD + co]);
        }
    };

    // group 0: Q + KV(0)
#pragma unroll
    for (int l = 0; l < 4; l++) {
        const int ch = tid + l * 256;
        const int r = ch >> 3, co = (ch & 7) * 8;
        cp_async16(&qs[r][co],
                   &qkv[((size_t)(b * N_TOK + row0 + r) * 3) * C_DIM + h * D_HEAD + co]);
    }
    load_kv(0, 0);
    CP_COMMIT();
    if (tid < QROWS) denom[tid] = 0.f;

    float acc_o[8][4];
#pragma unroll
    for (int i = 0; i < 8; i++)
#pragma unroll
        for (int t = 0; t < 4; t++) acc_o[i][t] = 0.f;

    const int NT = N_TOK / KTILE;   // 8
    for (int t = 0; t < NT; t++) {
        const int buf = t & 1;
        CP_WAIT(0);                 // KV(t) (and Q on t=0) resident
        __syncthreads();            // all warps past prior PV; loads visible

        if (t + 1 < NT) load_kv((t + 1) * KTILE, buf ^ 1);
        CP_COMMIT();                // overlaps everything below

        // ---- S = Q @ K^T : warp computes 32x64, k=64 ----
        float acc_s[2][8][4];
#pragma unroll
        for (int i = 0; i < 2; i++)
#pragma unroll
            for (int j = 0; j < 8; j++)
#pragma unroll
                for (int tt = 0; tt < 4; tt++) acc_s[i][j][tt] = 0.f;

#pragma unroll
        for (int kk = 0; kk < D_HEAD; kk += 16) {
            uint32_t aq[2][4];
#pragma unroll
            for (int mt = 0; mt < 2; mt++)
                ldsm_x4(aq[mt], &qs[sm0 + mt * 16 + (lane & 15)][kk + ((lane >> 4) << 3)]);
            uint32_t bk[4][4];
#pragma unroll
            for (int ntp = 0; ntp < 4; ntp++)
                ldsm_x4(bk[ntp], &ks[buf][sc0 + ntp * 16 + ((lane >> 4) << 3) + (lane & 7)]
                                         [kk + (((lane >> 3) & 1) << 3)]);
#pragma unroll
            for (int nt = 0; nt < 8; nt++) {
                const uint32_t* bb = &bk[nt >> 1][(nt & 1) * 2];
#pragma unroll
                for (int mt = 0; mt < 2; mt++)
                    mma_f16(acc_s[mt][nt], aq[mt], bb);
            }
        }

        // ---- f(s) = 1 + s + s^2/2 (>0), stage P, row sums ----
#pragma unroll
        for (int mt = 0; mt < 2; mt++) {
            const int r1 = sm0 + mt * 16 + grp, r2 = r1 + 8;
            float rs1 = 0.f, rs2 = 0.f;
#pragma unroll
            for (int nt = 0; nt < 8; nt++) {
                float fx, fy, fz, fw, v;
                v = acc_s[mt][nt][0]; fx = fmaf(0.5f * v, v, 1.f + v);
                v = acc_s[mt][nt][1]; fy = fmaf(0.5f * v, v, 1.f + v);
                v = acc_s[mt][nt][2]; fz = fmaf(0.5f * v, v, 1.f + v);
                v = acc_s[mt][nt][3]; fw = fmaf(0.5f * v, v, 1.f + v);
                rs1 += fx + fy;
                rs2 += fz + fw;
                const int col = sc0 + nt * 8 + 2 * qd;
                *(__half2*)&ps[r1][col] = __floats2half2_rn(fx, fy);
                *(__half2*)&ps[r2][col] = __floats2half2_rn(fz, fw);
            }
            rs1 += __shfl_xor_sync(0xffffffffu, rs1, 1);
            rs1 += __shfl_xor_sync(0xffffffffu, rs1, 2);
            rs2 += __shfl_xor_sync(0xffffffffu, rs2, 1);
            rs2 += __shfl_xor_sync(0xffffffffu, rs2, 2);
            if (qd == 0) {
                atomicAdd(&denom[r1], rs1);
                atomicAdd(&denom[r2], rs2);
            }
        }
        __syncthreads();            // ps complete before PV reads

        // ---- O += P @ V : warp 16x64, k=128; V via ldsm.trans ----
#pragma unroll
        for (int kk = 0; kk < KTILE; kk += 16) {
            uint32_t ap[4];
            ldsm_x4(ap, &ps[pm0 + (lane & 15)][kk + ((lane >> 4) << 3)]);
            uint32_t bv[4][4];
#pragma unroll
            for (int dp = 0; dp < 4; dp++)
                ldsm_x4_trans(bv[dp],
                    &vs[buf][kk + (((lane >> 3) & 1) << 3) + (lane & 7)]
                            [dp * 16 + ((lane >> 4) << 3)]);
#pragma unroll
            for (int nt = 0; nt < 8; nt++) {
                const uint32_t* bb = &bv[nt >> 1][(nt & 1) * 2];
                mma_f16(acc_o[nt], ap, bb);
            }
        }
    }
    __syncthreads();

    // ---- normalize + store fp16 ----
    const int r1 = pm0 + grp, r2 = r1 + 8;
    const float inv1 = 1.f / denom[r1];
    const float inv2 = 1.f / denom[r2];
#pragma unroll
    for (int nt = 0; nt < 8; nt++) {
        const int c = h * D_HEAD + nt * 8 + 2 * qd;
        const size_t base1 = (size_t)(b * N_TOK + row0 + r1) * C_DIM + c;
        const size_t base2 = (size_t)(b * N_TOK + row0 + r2) * C_DIM + c;
        *(__half2*)&out[base1] = __floats2half2_rn(acc_o[nt][0] * inv1, acc_o[nt][1] * inv1);
        *(__half2*)&out[base2] = __floats2half2_rn(acc_o[nt][2] * inv2, acc_o[nt][3] * inv2);
    }
}

// ============================================================
// launcher
// ============================================================
extern "C" void kernel_launch(void* const* d_in, const int* in_sizes, int n_in,
                              void* d_out, int out_size)
{
    const float* x      = (const float*)d_in[0];
    const float* w_qkv  = (const float*)d_in[1];
    const float* w_proj = (const float*)d_in[2];
    const float* b_proj = (const float*)d_in[3];
    float* out = (float*)d_out;

    __half *qkv_s, *attn_s, *xh_s, *wqkvT_s, *wprojT_s;
    cudaGetSymbolAddress((void**)&qkv_s,    g_qkv);
    cudaGetSymbolAddress((void**)&attn_s,   g_attn);
    cudaGetSymbolAddress((void**)&xh_s,     g_xh);
    cudaGetSymbolAddress((void**)&wqkvT_s,  g_wqkvT);
    cudaGetSymbolAddress((void**)&wprojT_s, g_wprojT);

    cudaFuncSetAttribute(gemm_f16, cudaFuncAttributeMaxDynamicSharedMemorySize,
                         (int)GEMM_SMEM_BYTES);
    cudaFuncSetAttribute(attn_f16, cudaFuncAttributeMaxDynamicSharedMemorySize,
                         (int)ATTN_SMEM_BYTES);

    const int M = B_SZ * N_TOK;  // 8192

    // ---- pre-pass: x -> fp16; transpose weights -> fp16 ----
    {
        const int n4 = (M * C_DIM) / 4;
        to_half_kernel<<<(n4 + 255) / 256, 256>>>(x, xh_s, n4);
        transpose_half_kernel<<<dim3(3 * C_DIM / 32, C_DIM / 32), dim3(32, 8)>>>(
            w_qkv, wqkvT_s, C_DIM, 3 * C_DIM);
        transpose_half_kernel<<<dim3(C_DIM / 32, C_DIM / 32), dim3(32, 8)>>>(
            w_proj, wprojT_s, C_DIM, C_DIM);
    }

    // 1) qkv = x @ w_qkv  (fp16 out, Q cols pre-scaled)
    gemm_f16<<<dim3(3 * C_DIM / 128, M / 128), 256, GEMM_SMEM_BYTES>>>(
        xh_s, wqkvT_s, nullptr, qkv_s, M, 3 * C_DIM, C_DIM, 0, 1);

    // 2) fused Taylor attention -> fp16
    attn_f16<<<dim3(N_TOK / QROWS, B_SZ * H_NUM), 256, ATTN_SMEM_BYTES>>>(qkv_s, attn_s);

    // 3) out = attn @ w_proj + b_proj  (fp32 out)
    gemm_f16<<<dim3(C_DIM / 128, M / 128), 256, GEMM_SMEM_BYTES>>>(
        attn_s, wprojT_s, b_proj, out, M, C_DIM, C_DIM, 1, 0);
}

// round 8
// speedup vs baseline: 8.6025x; 1.1403x over previous
#include <cuda_runtime.h>
#include <cuda_fp16.h>
#include <cstdint>
#include <cstddef>

// ---------------- problem constants ----------------
#define B_SZ   8
#define N_TOK  1024
#define C_DIM  768
#define H_NUM  12
#define D_HEAD 64
#define SCALE_Q 0.125f   // 64^-0.5

// ---------------- scratch (device globals; no cudaMalloc allowed) ----------------
__device__ __half g_qkv [(size_t)B_SZ * N_TOK * 3 * C_DIM];   // fp16, Q pre-scaled
__device__ __half g_attn[(size_t)B_SZ * N_TOK * C_DIM];       // fp16 attention out
__device__ __half g_xh  [(size_t)B_SZ * N_TOK * C_DIM];       // x -> fp16
__device__ __half g_wqkvT[(size_t)3 * C_DIM * C_DIM];         // w_qkv^T [2304][768] fp16
__device__ __half g_wprojT[(size_t)C_DIM * C_DIM];            // w_proj^T [768][768] fp16

// ---------------- helpers ----------------
__device__ __forceinline__ void mma_f16(float* d, const uint32_t* a, const uint32_t* b) {
    asm volatile(
        "mma.sync.aligned.m16n8k16.row.col.f32.f16.f16.f32 "
        "{%0,%1,%2,%3}, {%4,%5,%6,%7}, {%8,%9}, {%0,%1,%2,%3};"
        : "+f"(d[0]), "+f"(d[1]), "+f"(d[2]), "+f"(d[3])
        : "r"(a[0]), "r"(a[1]), "r"(a[2]), "r"(a[3]),
          "r"(b[0]), "r"(b[1]));
}

__device__ __forceinline__ void ldsm_x4(uint32_t* r, const __half* p) {
    uint32_t addr = (uint32_t)__cvta_generic_to_shared(p);
    asm volatile(
        "ldmatrix.sync.aligned.m8n8.x4.shared.b16 {%0,%1,%2,%3}, [%4];"
        : "=r"(r[0]), "=r"(r[1]), "=r"(r[2]), "=r"(r[3]) : "r"(addr));
}

__device__ __forceinline__ void ldsm_x4_trans(uint32_t* r, const __half* p) {
    uint32_t addr = (uint32_t)__cvta_generic_to_shared(p);
    asm volatile(
        "ldmatrix.sync.aligned.m8n8.x4.trans.shared.b16 {%0,%1,%2,%3}, [%4];"
        : "=r"(r[0]), "=r"(r[1]), "=r"(r[2]), "=r"(r[3]) : "r"(addr));
}

__device__ __forceinline__ void cp_async16(void* smem_dst, const void* gmem_src) {
    uint32_t a = (uint32_t)__cvta_generic_to_shared(smem_dst);
    asm volatile("cp.async.cg.shared.global [%0], [%1], 16;" :: "r"(a), "l"(gmem_src));
}
#define CP_COMMIT()  asm volatile("cp.async.commit_group;")
#define CP_WAIT(n)   asm volatile("cp.async.wait_group %0;" :: "n"(n))

__device__ __forceinline__ uint32_t packh2(float a, float b) {
    __half2 h = __floats2half2_rn(a, b);
    return *(uint32_t*)&h;
}

// ============================================================
// pre-pass kernels
// ============================================================
__global__ __launch_bounds__(256) void to_half_kernel(
    const float* __restrict__ in, __half* __restrict__ out, int n4)
{
    const int i = blockIdx.x * 256 + threadIdx.x;
    if (i >= n4) return;
    float4 v = ((const float4*)in)[i];
    __half2* o = (__half2*)(out + (size_t)i * 4);
    o[0] = __floats2half2_rn(v.x, v.y);
    o[1] = __floats2half2_rn(v.z, v.w);
}

__global__ __launch_bounds__(256) void transpose_half_kernel(
    const float* __restrict__ in, __half* __restrict__ out, int R, int Ncols)
{
    __shared__ float tile[32][33];
    const int bx = blockIdx.x * 32, by = blockIdx.y * 32;
    const int tx = threadIdx.x, ty = threadIdx.y;
#pragma unroll
    for (int j = 0; j < 32; j += 8)
        tile[ty + j][tx] = in[(size_t)(by + ty + j) * Ncols + bx + tx];
    __syncthreads();
#pragma unroll
    for (int j = 0; j < 32; j += 8)
        out[(size_t)(bx + ty + j) * R + by + tx] = __float2half_rn(tile[tx][ty + j]);
}

// ============================================================
// FP16 GEMM: C[M,N] = A[M,K] @ BT[N,K]^T. 128x128x32 tile,
// 5-stage cp.async ring, one barrier per k-tile, m16n8k16.
// (unchanged from R7 — at legacy-HMMA ceiling)
// ============================================================
#define GPITCH 40
#define STAGES 5
#define GEMM_SMEM_BYTES (STAGES * 2 * 128 * GPITCH * 2)

__global__ __launch_bounds__(256, 2) void gemm_f16(
    const __half* __restrict__ A, const __half* __restrict__ BT,
    const float* __restrict__ bias, void* __restrict__ Cout,
    int M, int N, int K, int has_bias, int out_half)
{
    extern __shared__ __half smh[];
    __half (*As)[128][GPITCH] = (__half(*)[128][GPITCH])(smh);
    __half (*Bs)[128][GPITCH] = (__half(*)[128][GPITCH])(smh + STAGES * 128 * GPITCH);

    const int tid  = threadIdx.x;
    const int wid  = tid >> 5;
    const int lane = tid & 31;
    const int grp  = lane >> 2;
    const int qd   = lane & 3;

    const int brow = blockIdx.y * 128;
    const int bcol = blockIdx.x * 128;
    const int m_base = (wid & 1) * 64;
    const int n_base = (wid >> 1) * 32;

    float acc[4][4][4];
#pragma unroll
    for (int i = 0; i < 4; i++)
#pragma unroll
        for (int j = 0; j < 4; j++)
#pragma unroll
            for (int t = 0; t < 4; t++) acc[i][j][t] = 0.f;

    auto load_tile = [&](int t, int s) {
        const int k0 = t * 32;
#pragma unroll
        for (int i = 0; i < 2; i++) {
            const int ch = tid + i * 256;
            const int r = ch >> 2, co = (ch & 3) * 8;
            cp_async16(&As[s][r][co], &A [(size_t)(brow + r) * K + k0 + co]);
            cp_async16(&Bs[s][r][co], &BT[(size_t)(bcol + r) * K + k0 + co]);
        }
    };

    const int T = K / 32;
#pragma unroll
    for (int t = 0; t < STAGES - 1; t++) {
        if (t < T) load_tile(t, t);
        CP_COMMIT();
    }

    int buf = 0, lbuf = (STAGES - 1) % STAGES;
    for (int t = 0; t < T; t++) {
        CP_WAIT(STAGES - 2);
        __syncthreads();
        if (t + STAGES - 1 < T) load_tile(t + STAGES - 1, lbuf);
        CP_COMMIT();

#pragma unroll
        for (int ks = 0; ks < 32; ks += 16) {
            uint32_t af[4][4];
#pragma unroll
            for (int mt = 0; mt < 4; mt++)
                ldsm_x4(af[mt], &As[buf][m_base + mt * 16 + (lane & 15)][ks + ((lane >> 4) << 3)]);
            uint32_t bf[2][4];
#pragma unroll
            for (int ntp = 0; ntp < 2; ntp++)
                ldsm_x4(bf[ntp], &Bs[buf][n_base + ntp * 16 + ((lane >> 4) << 3) + (lane & 7)]
                                         [ks + (((lane >> 3) & 1) << 3)]);
#pragma unroll
            for (int nt = 0; nt < 4; nt++) {
                const uint32_t* bb = &bf[nt >> 1][(nt & 1) * 2];
#pragma unroll
                for (int mt = 0; mt < 4; mt++)
                    mma_f16(acc[mt][nt], af[mt], bb);
            }
        }
        if (++buf == STAGES) buf = 0;
        if (++lbuf == STAGES) lbuf = 0;
    }

#pragma unroll
    for (int mt = 0; mt < 4; mt++) {
        const int r1 = brow + m_base + mt * 16 + grp;
        const int r2 = r1 + 8;
#pragma unroll
        for (int nt = 0; nt < 4; nt++) {
            const int c = bcol + n_base + nt * 8 + 2 * qd;
            float v0 = acc[mt][nt][0], v1 = acc[mt][nt][1];
            float v2 = acc[mt][nt][2], v3 = acc[mt][nt][3];
            if (out_half) {
                const float s = (c < C_DIM) ? SCALE_Q : 1.f;
                __half* Ch = (__half*)Cout;
                *(__half2*)&Ch[(size_t)r1 * N + c] = __floats2half2_rn(v0 * s, v1 * s);
                *(__half2*)&Ch[(size_t)r2 * N + c] = __floats2half2_rn(v2 * s, v3 * s);
            } else {
                float b0 = 0.f, b1 = 0.f;
                if (has_bias) { b0 = __ldg(&bias[c]); b1 = __ldg(&bias[c + 1]); }
                float* Cf = (float*)Cout;
                *(float2*)&Cf[(size_t)r1 * N + c] = make_float2(v0 + b0, v1 + b1);
                *(float2*)&Cf[(size_t)r2 * N + c] = make_float2(v2 + b0, v3 + b1);
            }
        }
    }
}

// ============================================================
// Fused Taylor attention — FA2-style register repack.
// block = 128 threads (4 warps), Q tile 64 rows, KV tile 128,
// double-buffered K/V. Each warp owns 16 Q-rows x all 128 S-cols;
// P stays in registers (C-frag -> A-frag repack), denom in regs.
// grid = (16, 96).
// ============================================================
#define QROWS 64
#define KTILE 128
#define HPITCH 72    // 64+8 halves = 144B pitch

#define AQS_OFF 0
#define AKS_OFF (AQS_OFF + QROWS * HPITCH)
#define AVS_OFF (AKS_OFF + 2 * KTILE * HPITCH)
#define ATTN_SMEM_HALVES (AVS_OFF + 2 * KTILE * HPITCH)
#define ATTN_SMEM_BYTES  (ATTN_SMEM_HALVES * 2)   // 82944

__global__ __launch_bounds__(128, 2) void attn_f16(
    const __half* __restrict__ qkv, __half* __restrict__ out)
{
    extern __shared__ __half smh[];
    __half (*qs)[HPITCH] = (__half(*)[HPITCH])(smh + AQS_OFF);
    __half (*ks)[KTILE][HPITCH] = (__half(*)[KTILE][HPITCH])(smh + AKS_OFF);
    __half (*vs)[KTILE][HPITCH] = (__half(*)[KTILE][HPITCH])(smh + AVS_OFF);

    const int tid  = threadIdx.x;
    const int wid  = tid >> 5;
    const int lane = tid & 31;
    const int grp  = lane >> 2;
    const int qd   = lane & 3;

    const int b    = blockIdx.y / H_NUM;
    const int h    = blockIdx.y % H_NUM;
    const int row0 = blockIdx.x * QROWS;

    const int pm0 = wid * 16;   // warp's 16 Q-rows

    auto load_kv = [&](int m0, int s) {
#pragma unroll
        for (int l = 0; l < 8; l++) {
            const int ch = tid + l * 128;
            const int r = ch >> 3, co = (ch & 7) * 8;
            const size_t nb = (size_t)(b * N_TOK + m0 + r) * 3;
            cp_async16(&ks[s][r][co], &qkv[(nb + 1) * C_DIM + h * D_HEAD + co]);
            cp_async16(&vs[s][r][co], &qkv[(nb + 2) * C_DIM + h * D_HEAD + co]);
        }
    };

    // prologue: Q + KV(0)
#pragma unroll
    for (int l = 0; l < 4; l++) {
        const int ch = tid + l * 128;
        const int r = ch >> 3, co = (ch & 7) * 8;
        cp_async16(&qs[r][co],
                   &qkv[((size_t)(b * N_TOK + row0 + r) * 3) * C_DIM + h * D_HEAD + co]);
    }
    load_kv(0, 0);
    CP_COMMIT();
    CP_WAIT(0);
    __syncthreads();

    // hoist Q fragments (loop-invariant): 4 kk-steps x 4 regs
    uint32_t aq[4][4];
#pragma unroll
    for (int kk4 = 0; kk4 < 4; kk4++)
        ldsm_x4(aq[kk4], &qs[pm0 + (lane & 15)][kk4 * 16 + ((lane >> 4) << 3)]);

    float acc_o[8][4];
#pragma unroll
    for (int i = 0; i < 8; i++)
#pragma unroll
        for (int t = 0; t < 4; t++) acc_o[i][t] = 0.f;
    float dn0 = 0.f, dn1 = 0.f;   // denom for rows pm0+grp, pm0+grp+8

    const int NT = N_TOK / KTILE;   // 8
    for (int t = 0; t < NT; t++) {
        const int buf = t & 1;
        if (t > 0) {
            CP_WAIT(0);          // KV(t) resident
            __syncthreads();     // all warps done with buf (tile t-2's buffer)
        }
        if (t + 1 < NT) load_kv((t + 1) * KTILE, buf ^ 1);
        CP_COMMIT();

        // ---- S = Q @ K^T : warp computes 16 x 128, k = 64 ----
        float acc_s[16][4];
#pragma unroll
        for (int i = 0; i < 16; i++)
#pragma unroll
            for (int tt = 0; tt < 4; tt++) acc_s[i][tt] = 0.f;

#pragma unroll
        for (int kk4 = 0; kk4 < 4; kk4++) {
            uint32_t bk[8][4];
#pragma unroll
            for (int ntp = 0; ntp < 8; ntp++)
                ldsm_x4(bk[ntp], &ks[buf][ntp * 16 + ((lane >> 4) << 3) + (lane & 7)]
                                         [kk4 * 16 + (((lane >> 3) & 1) << 3)]);
#pragma unroll
            for (int nt = 0; nt < 16; nt++)
                mma_f16(acc_s[nt], aq[kk4], &bk[nt >> 1][(nt & 1) * 2]);
        }

        // ---- f(s) = 1 + s + s^2/2 (>0) in place; accumulate denom ----
#pragma unroll
        for (int nt = 0; nt < 16; nt++) {
            float v;
            v = acc_s[nt][0]; acc_s[nt][0] = fmaf(0.5f * v, v, 1.f + v);
            v = acc_s[nt][1]; acc_s[nt][1] = fmaf(0.5f * v, v, 1.f + v);
            v = acc_s[nt][2]; acc_s[nt][2] = fmaf(0.5f * v, v, 1.f + v);
            v = acc_s[nt][3]; acc_s[nt][3] = fmaf(0.5f * v, v, 1.f + v);
            dn0 += acc_s[nt][0] + acc_s[nt][1];
            dn1 += acc_s[nt][2] + acc_s[nt][3];
        }

        // ---- O += P @ V : P from register repack (C-frag -> A-frag) ----
#pragma unroll
        for (int kc = 0; kc < 8; kc++) {
            uint32_t ap[4];
            ap[0] = packh2(acc_s[2 * kc    ][0], acc_s[2 * kc    ][1]);
            ap[1] = packh2(acc_s[2 * kc    ][2], acc_s[2 * kc    ][3]);
            ap[2] = packh2(acc_s[2 * kc + 1][0], acc_s[2 * kc + 1][1]);
            ap[3] = packh2(acc_s[2 * kc + 1][2], acc_s[2 * kc + 1][3]);
            uint32_t bv[4][4];
#pragma unroll
            for (int dp = 0; dp < 4; dp++)
                ldsm_x4_trans(bv[dp],
                    &vs[buf][kc * 16 + (((lane >> 3) & 1) << 3) + (lane & 7)]
                            [dp * 16 + ((lane >> 4) << 3)]);
#pragma unroll
            for (int nt = 0; nt < 8; nt++)
                mma_f16(acc_o[nt], ap, &bv[nt >> 1][(nt & 1) * 2]);
        }
    }

    // ---- finalize denom (full row is within this warp) ----
    dn0 += __shfl_xor_sync(0xffffffffu, dn0, 1);
    dn0 += __shfl_xor_sync(0xffffffffu, dn0, 2);
    dn1 += __shfl_xor_sync(0xffffffffu, dn1, 1);
    dn1 += __shfl_xor_sync(0xffffffffu, dn1, 2);
    const float inv1 = 1.f / dn0;
    const float inv2 = 1.f / dn1;

    // ---- store fp16 ----
    const int r1 = pm0 + grp, r2 = r1 + 8;
#pragma unroll
    for (int nt = 0; nt < 8; nt++) {
        const int c = h * D_HEAD + nt * 8 + 2 * qd;
        const size_t base1 = (size_t)(b * N_TOK + row0 + r1) * C_DIM + c;
        const size_t base2 = (size_t)(b * N_TOK + row0 + r2) * C_DIM + c;
        *(__half2*)&out[base1] = __floats2half2_rn(acc_o[nt][0] * inv1, acc_o[nt][1] * inv1);
        *(__half2*)&out[base2] = __floats2half2_rn(acc_o[nt][2] * inv2, acc_o[nt][3] * inv2);
    }
}

// ============================================================
// launcher
// ============================================================
extern "C" void kernel_launch(void* const* d_in, const int* in_sizes, int n_in,
                              void* d_out, int out_size)
{
    const float* x      = (const float*)d_in[0];
    const float* w_qkv  = (const float*)d_in[1];
    const float* w_proj = (const float*)d_in[2];
    const float* b_proj = (const float*)d_in[3];
    float* out = (float*)d_out;

    __half *qkv_s, *attn_s, *xh_s, *wqkvT_s, *wprojT_s;
    cudaGetSymbolAddress((void**)&qkv_s,    g_qkv);
    cudaGetSymbolAddress((void**)&attn_s,   g_attn);
    cudaGetSymbolAddress((void**)&xh_s,     g_xh);
    cudaGetSymbolAddress((void**)&wqkvT_s,  g_wqkvT);
    cudaGetSymbolAddress((void**)&wprojT_s, g_wprojT);

    cudaFuncSetAttribute(gemm_f16, cudaFuncAttributeMaxDynamicSharedMemorySize,
                         (int)GEMM_SMEM_BYTES);
    cudaFuncSetAttribute(attn_f16, cudaFuncAttributeMaxDynamicSharedMemorySize,
                         (int)ATTN_SMEM_BYTES);

    const int M = B_SZ * N_TOK;  // 8192

    // ---- pre-pass: x -> fp16; transpose weights -> fp16 ----
    {
        const int n4 = (M * C_DIM) / 4;
        to_half_kernel<<<(n4 + 255) / 256, 256>>>(x, xh_s, n4);
        transpose_half_kernel<<<dim3(3 * C_DIM / 32, C_DIM / 32), dim3(32, 8)>>>(
            w_qkv, wqkvT_s, C_DIM, 3 * C_DIM);
        transpose_half_kernel<<<dim3(C_DIM / 32, C_DIM / 32), dim3(32, 8)>>>(
            w_proj, wprojT_s, C_DIM, C_DIM);
    }

    // 1) qkv = x @ w_qkv  (fp16 out, Q cols pre-scaled)
    gemm_f16<<<dim3(3 * C_DIM / 128, M / 128), 256, GEMM_SMEM_BYTES>>>(
        xh_s, wqkvT_s, nullptr, qkv_s, M, 3 * C_DIM, C_DIM, 0, 1);

    // 2) fused Taylor attention -> fp16  (128 threads, reg-repack)
    attn_f16<<<dim3(N_TOK / QROWS, B_SZ * H_NUM), 128, ATTN_SMEM_BYTES>>>(qkv_s, attn_s);

    // 3) out = attn @ w_proj + b_proj  (fp32 out)
    gemm_f16<<<dim3(C_DIM / 128, M / 128), 256, GEMM_SMEM_BYTES>>>(
        attn_s, wprojT_s, b_proj, out, M, C_DIM, C_DIM, 1, 0);
}

// round 9
// speedup vs baseline: 9.4324x; 1.0965x over previous
#include <cuda_runtime.h>
#include <cuda_fp16.h>
#include <cstdint>
#include <cstddef>

// ---------------- problem constants ----------------
#define B_SZ   8
#define N_TOK  1024
#define C_DIM  768
#define H_NUM  12
#define D_HEAD 64
#define SCALE_Q 0.125f   // 64^-0.5

// ---------------- scratch (device globals; no cudaMalloc allowed) ----------------
__device__ __half g_qkv [(size_t)B_SZ * N_TOK * 3 * C_DIM];   // fp16, Q pre-scaled
__device__ __half g_attn[(size_t)B_SZ * N_TOK * C_DIM];       // fp16 attention out
__device__ __half g_xh  [(size_t)B_SZ * N_TOK * C_DIM];       // x -> fp16
__device__ __half g_wqkvT[(size_t)3 * C_DIM * C_DIM];         // w_qkv^T [2304][768] fp16
__device__ __half g_wprojT[(size_t)C_DIM * C_DIM];            // w_proj^T [768][768] fp16

// ---------------- helpers ----------------
__device__ __forceinline__ void mma_f16(float* d, const uint32_t* a, const uint32_t* b) {
    asm volatile(
        "mma.sync.aligned.m16n8k16.row.col.f32.f16.f16.f32 "
        "{%0,%1,%2,%3}, {%4,%5,%6,%7}, {%8,%9}, {%0,%1,%2,%3};"
        : "+f"(d[0]), "+f"(d[1]), "+f"(d[2]), "+f"(d[3])
        : "r"(a[0]), "r"(a[1]), "r"(a[2]), "r"(a[3]),
          "r"(b[0]), "r"(b[1]));
}

__device__ __forceinline__ void ldsm_x4(uint32_t* r, const void* p) {
    uint32_t addr = (uint32_t)__cvta_generic_to_shared(p);
    asm volatile(
        "ldmatrix.sync.aligned.m8n8.x4.shared.b16 {%0,%1,%2,%3}, [%4];"
        : "=r"(r[0]), "=r"(r[1]), "=r"(r[2]), "=r"(r[3]) : "r"(addr));
}

__device__ __forceinline__ void ldsm_x4_trans(uint32_t* r, const void* p) {
    uint32_t addr = (uint32_t)__cvta_generic_to_shared(p);
    asm volatile(
        "ldmatrix.sync.aligned.m8n8.x4.trans.shared.b16 {%0,%1,%2,%3}, [%4];"
        : "=r"(r[0]), "=r"(r[1]), "=r"(r[2]), "=r"(r[3]) : "r"(addr));
}

__device__ __forceinline__ void cp_async16(void* smem_dst, const void* gmem_src) {
    uint32_t a = (uint32_t)__cvta_generic_to_shared(smem_dst);
    asm volatile("cp.async.cg.shared.global [%0], [%1], 16;" :: "r"(a), "l"(gmem_src));
}
#define CP_COMMIT()  asm volatile("cp.async.commit_group;")
#define CP_WAIT(n)   asm volatile("cp.async.wait_group %0;" :: "n"(n))

__device__ __forceinline__ uint32_t packh2(float a, float b) {
    __half2 h = __floats2half2_rn(a, b);
    return *(uint32_t*)&h;
}

// SW128 swizzle on byte offsets (rows of 128B)
__device__ __forceinline__ char* swz(char* base, int byteoff) {
    return base + (byteoff ^ ((byteoff >> 3) & 0x70));
}

// ============================================================
// fused pre-pass: x->fp16 | transpose w_qkv | transpose w_proj
// ============================================================
#define PP_XBLKS  ((B_SZ * N_TOK * C_DIM / 4 + 255) / 256)          // 6144
#define PP_WQBLKS ((3 * C_DIM / 32) * (C_DIM / 32))                 // 1728
#define PP_WPBLKS ((C_DIM / 32) * (C_DIM / 32))                     // 576

__global__ __launch_bounds__(256) void prepass_kernel(
    const float* __restrict__ x,     __half* __restrict__ xh,
    const float* __restrict__ wqkv,  __half* __restrict__ wqkvT,
    const float* __restrict__ wproj, __half* __restrict__ wprojT)
{
    const int blk = blockIdx.x;
    const int tid = threadIdx.x;
    if (blk < PP_XBLKS) {
        const int i = blk * 256 + tid;
        float4 v = ((const float4*)x)[i];
        __half2* o = (__half2*)(xh + (size_t)i * 4);
        o[0] = __floats2half2_rn(v.x, v.y);
        o[1] = __floats2half2_rn(v.z, v.w);
        return;
    }
    __shared__ float tile[32][33];
    const float* in;
    __half* outp;
    int R, Ncols, bi;
    if (blk < PP_XBLKS + PP_WQBLKS) {
        bi = blk - PP_XBLKS; in = wqkv; outp = wqkvT; R = C_DIM; Ncols = 3 * C_DIM;
    } else {
        bi = blk - PP_XBLKS - PP_WQBLKS; in = wproj; outp = wprojT; R = C_DIM; Ncols = C_DIM;
    }
    const int nbx = Ncols / 32;
    const int bx = (bi % nbx) * 32, by = (bi / nbx) * 32;
    const int tx = tid & 31, ty = tid >> 5;
#pragma unroll
    for (int j = 0; j < 32; j += 8)
        tile[ty + j][tx] = in[(size_t)(by + ty + j) * Ncols + bx + tx];
    __syncthreads();
#pragma unroll
    for (int j = 0; j < 32; j += 8)
        outp[(size_t)(bx + ty + j) * R + by + tx] = __float2half_rn(tile[tx][ty + j]);
}

// ============================================================
// FP16 GEMM (unchanged — at legacy-HMMA ceiling)
// ============================================================
#define GPITCH 40
#define STAGES 5
#define GEMM_SMEM_BYTES (STAGES * 2 * 128 * GPITCH * 2)

__global__ __launch_bounds__(256, 2) void gemm_f16(
    const __half* __restrict__ A, const __half* __restrict__ BT,
    const float* __restrict__ bias, void* __restrict__ Cout,
    int M, int N, int K, int has_bias, int out_half)
{
    extern __shared__ __half smh[];
    __half (*As)[128][GPITCH] = (__half(*)[128][GPITCH])(smh);
    __half (*Bs)[128][GPITCH] = (__half(*)[128][GPITCH])(smh + STAGES * 128 * GPITCH);

    const int tid  = threadIdx.x;
    const int wid  = tid >> 5;
    const int lane = tid & 31;
    const int grp  = lane >> 2;
    const int qd   = lane & 3;

    const int brow = blockIdx.y * 128;
    const int bcol = blockIdx.x * 128;
    const int m_base = (wid & 1) * 64;
    const int n_base = (wid >> 1) * 32;

    float acc[4][4][4];
#pragma unroll
    for (int i = 0; i < 4; i++)
#pragma unroll
        for (int j = 0; j < 4; j++)
#pragma unroll
            for (int t = 0; t < 4; t++) acc[i][j][t] = 0.f;

    auto load_tile = [&](int t, int s) {
        const int k0 = t * 32;
#pragma unroll
        for (int i = 0; i < 2; i++) {
            const int ch = tid + i * 256;
            const int r = ch >> 2, co = (ch & 3) * 8;
            cp_async16(&As[s][r][co], &A [(size_t)(brow + r) * K + k0 + co]);
            cp_async16(&Bs[s][r][co], &BT[(size_t)(bcol + r) * K + k0 + co]);
        }
    };

    const int T = K / 32;
#pragma unroll
    for (int t = 0; t < STAGES - 1; t++) {
        if (t < T) load_tile(t, t);
        CP_COMMIT();
    }

    int buf = 0, lbuf = (STAGES - 1) % STAGES;
    for (int t = 0; t < T; t++) {
        CP_WAIT(STAGES - 2);
        __syncthreads();
        if (t + STAGES - 1 < T) load_tile(t + STAGES - 1, lbuf);
        CP_COMMIT();

#pragma unroll
        for (int ks = 0; ks < 32; ks += 16) {
            uint32_t af[4][4];
#pragma unroll
            for (int mt = 0; mt < 4; mt++)
                ldsm_x4(af[mt], &As[buf][m_base + mt * 16 + (lane & 15)][ks + ((lane >> 4) << 3)]);
            uint32_t bf[2][4];
#pragma unroll
            for (int ntp = 0; ntp < 2; ntp++)
                ldsm_x4(bf[ntp], &Bs[buf][n_base + ntp * 16 + ((lane >> 4) << 3) + (lane & 7)]
                                         [ks + (((lane >> 3) & 1) << 3)]);
#pragma unroll
            for (int nt = 0; nt < 4; nt++) {
                const uint32_t* bb = &bf[nt >> 1][(nt & 1) * 2];
#pragma unroll
                for (int mt = 0; mt < 4; mt++)
                    mma_f16(acc[mt][nt], af[mt], bb);
            }
        }
        if (++buf == STAGES) buf = 0;
        if (++lbuf == STAGES) lbuf = 0;
    }

#pragma unroll
    for (int mt = 0; mt < 4; mt++) {
        const int r1 = brow + m_base + mt * 16 + grp;
        const int r2 = r1 + 8;
#pragma unroll
        for (int nt = 0; nt < 4; nt++) {
            const int c = bcol + n_base + nt * 8 + 2 * qd;
            float v0 = acc[mt][nt][0], v1 = acc[mt][nt][1];
            float v2 = acc[mt][nt][2], v3 = acc[mt][nt][3];
            if (out_half) {
                const float s = (c < C_DIM) ? SCALE_Q : 1.f;
                __half* Ch = (__half*)Cout;
                *(__half2*)&Ch[(size_t)r1 * N + c] = __floats2half2_rn(v0 * s, v1 * s);
                *(__half2*)&Ch[(size_t)r2 * N + c] = __floats2half2_rn(v2 * s, v3 * s);
            } else {
                float b0 = 0.f, b1 = 0.f;
                if (has_bias) { b0 = __ldg(&bias[c]); b1 = __ldg(&bias[c + 1]); }
                float* Cf = (float*)Cout;
                *(float2*)&Cf[(size_t)r1 * N + c] = make_float2(v0 + b0, v1 + b1);
                *(float2*)&Cf[(size_t)r2 * N + c] = make_float2(v2 + b0, v3 + b1);
            }
        }
    }
}

// ============================================================
// Fused Taylor attention — register repack + SW128 smem (no pad),
// Q buffer aliased onto KV buf1, 3 CTAs/SM.
// block = 128 threads (4 warps), Q tile 64, KV tile 128 (double-buf).
// g(s) = (s+1)^2 + 1 = 2*f(s) — scale cancels in normalization.
// smem layout (bytes): [K0:16K][V0:16K][K1(=Q):16K][V1:16K] = 64 KB
// ============================================================
#define QROWS 64
#define KTILE 128
#define TILE_B 16384
#define ATTN_SMEM_BYTES (4 * TILE_B)

__global__ __launch_bounds__(128, 3) void attn_f16(
    const __half* __restrict__ qkv, __half* __restrict__ out)
{
    extern __shared__ char smc[];
    char* const kbuf[2] = { smc,              smc + 2 * TILE_B };
    char* const vbuf[2] = { smc + TILE_B,     smc + 3 * TILE_B };
    char* const qbuf    = smc + 2 * TILE_B;   // alias: K1 region

    const int tid  = threadIdx.x;
    const int wid  = tid >> 5;
    const int lane = tid & 31;
    const int grp  = lane >> 2;
    const int qd   = lane & 3;

    const int b    = blockIdx.y / H_NUM;
    const int h    = blockIdx.y % H_NUM;
    const int row0 = blockIdx.x * QROWS;

    const int pm0 = wid * 16;   // warp's 16 Q-rows

    auto load_kv = [&](int m0, int s) {
#pragma unroll
        for (int l = 0; l < 8; l++) {
            const int ch = tid + l * 128;
            const int r = ch >> 3, cb = (ch & 7) * 16;      // byte col
            const size_t nb = (size_t)(b * N_TOK + m0 + r) * 3;
            cp_async16(swz(kbuf[s], r * 128 + cb), &qkv[(nb + 1) * C_DIM + h * D_HEAD + cb / 2]);
            cp_async16(swz(vbuf[s], r * 128 + cb), &qkv[(nb + 2) * C_DIM + h * D_HEAD + cb / 2]);
        }
    };

    // prologue: Q (into qbuf) + KV(0)
#pragma unroll
    for (int l = 0; l < 4; l++) {
        const int ch = tid + l * 128;
        const int r = ch >> 3, cb = (ch & 7) * 16;
        cp_async16(swz(qbuf, r * 128 + cb),
                   &qkv[((size_t)(b * N_TOK + row0 + r) * 3) * C_DIM + h * D_HEAD + cb / 2]);
    }
    load_kv(0, 0);
    CP_COMMIT();
    CP_WAIT(0);
    __syncthreads();

    // hoist Q fragments, then free qbuf for KV buf1
    uint32_t aq[4][4];
#pragma unroll
    for (int kk4 = 0; kk4 < 4; kk4++)
        ldsm_x4(aq[kk4], swz(qbuf, (pm0 + (lane & 15)) * 128
                                   + (kk4 * 16 + ((lane >> 4) << 3)) * 2));
    __syncthreads();   // all warps have aq before buf1 gets overwritten

    float acc_o[8][4];
#pragma unroll
    for (int i = 0; i < 8; i++)
#pragma unroll
        for (int t = 0; t < 4; t++) acc_o[i][t] = 0.f;
    float dn0a = 0.f, dn0b = 0.f, dn1a = 0.f, dn1b = 0.f;

    const int NT = N_TOK / KTILE;   // 8
    for (int t = 0; t < NT; t++) {
        const int buf = t & 1;
        if (t > 0) {
            CP_WAIT(0);
            __syncthreads();
        }
        if (t + 1 < NT) load_kv((t + 1) * KTILE, buf ^ 1);
        CP_COMMIT();

        // ---- S = Q @ K^T : warp computes 16 x 128, k = 64 ----
        float acc_s[16][4];
#pragma unroll
        for (int i = 0; i < 16; i++)
#pragma unroll
            for (int tt = 0; tt < 4; tt++) acc_s[i][tt] = 0.f;

#pragma unroll
        for (int kk4 = 0; kk4 < 4; kk4++) {
            uint32_t bk[8][4];
#pragma unroll
            for (int ntp = 0; ntp < 8; ntp++)
                ldsm_x4(bk[ntp], swz(kbuf[buf],
                    (ntp * 16 + ((lane >> 4) << 3) + (lane & 7)) * 128
                    + (kk4 * 16 + (((lane >> 3) & 1) << 3)) * 2));
#pragma unroll
            for (int nt = 0; nt < 16; nt++)
                mma_f16(acc_s[nt], aq[kk4], &bk[nt >> 1][(nt & 1) * 2]);
        }

        // ---- g(s) = (s+1)^2 + 1 in place; accumulate denom ----
#pragma unroll
        for (int nt = 0; nt < 16; nt++) {
            float u;
            u = acc_s[nt][0] + 1.f; acc_s[nt][0] = fmaf(u, u, 1.f);
            u = acc_s[nt][1] + 1.f; acc_s[nt][1] = fmaf(u, u, 1.f);
            u = acc_s[nt][2] + 1.f; acc_s[nt][2] = fmaf(u, u, 1.f);
            u = acc_s[nt][3] + 1.f; acc_s[nt][3] = fmaf(u, u, 1.f);
            if (nt & 1) {
                dn0b += acc_s[nt][0] + acc_s[nt][1];
                dn1b += acc_s[nt][2] + acc_s[nt][3];
            } else {
                dn0a += acc_s[nt][0] + acc_s[nt][1];
                dn1a += acc_s[nt][2] + acc_s[nt][3];
            }
        }

        // ---- O += P @ V : P via register repack (C-frag -> A-frag) ----
#pragma unroll
        for (int kc = 0; kc < 8; kc++) {
            uint32_t ap[4];
            ap[0] = packh2(acc_s[2 * kc    ][0], acc_s[2 * kc    ][1]);
            ap[1] = packh2(acc_s[2 * kc    ][2], acc_s[2 * kc    ][3]);
            ap[2] = packh2(acc_s[2 * kc + 1][0], acc_s[2 * kc + 1][1]);
            ap[3] = packh2(acc_s[2 * kc + 1][2], acc_s[2 * kc + 1][3]);
            uint32_t bv[4][4];
#pragma unroll
            for (int dp = 0; dp < 4; dp++)
                ldsm_x4_trans(bv[dp], swz(vbuf[buf],
                    (kc * 16 + (((lane >> 3) & 1) << 3) + (lane & 7)) * 128
                    + (dp * 16 + ((lane >> 4) << 3)) * 2));
#pragma unroll
            for (int nt = 0; nt < 8; nt++)
                mma_f16(acc_o[nt], ap, &bv[nt >> 1][(nt & 1) * 2]);
        }
    }

    // ---- finalize denom (full row within this warp) ----
    float dn0 = dn0a + dn0b;
    float dn1 = dn1a + dn1b;
    dn0 += __shfl_xor_sync(0xffffffffu, dn0, 1);
    dn0 += __shfl_xor_sync(0xffffffffu, dn0, 2);
    dn1 += __shfl_xor_sync(0xffffffffu, dn1, 1);
    dn1 += __shfl_xor_sync(0xffffffffu, dn1, 2);
    const float inv1 = 1.f / dn0;
    const float inv2 = 1.f / dn1;

    // ---- store fp16 ----
    const int r1 = pm0 + grp, r2 = r1 + 8;
#pragma unroll
    for (int nt = 0; nt < 8; nt++) {
        const int c = h * D_HEAD + nt * 8 + 2 * qd;
        const size_t base1 = (size_t)(b * N_TOK + row0 + r1) * C_DIM + c;
        const size_t base2 = (size_t)(b * N_TOK + row0 + r2) * C_DIM + c;
        *(__half2*)&out[base1] = __floats2half2_rn(acc_o[nt][0] * inv1, acc_o[nt][1] * inv1);
        *(__half2*)&out[base2] = __floats2half2_rn(acc_o[nt][2] * inv2, acc_o[nt][3] * inv2);
    }
}

// ============================================================
// launcher
// ============================================================
extern "C" void kernel_launch(void* const* d_in, const int* in_sizes, int n_in,
                              void* d_out, int out_size)
{
    const float* x      = (const float*)d_in[0];
    const float* w_qkv  = (const float*)d_in[1];
    const float* w_proj = (const float*)d_in[2];
    const float* b_proj = (const float*)d_in[3];
    float* out = (float*)d_out;

    __half *qkv_s, *attn_s, *xh_s, *wqkvT_s, *wprojT_s;
    cudaGetSymbolAddress((void**)&qkv_s,    g_qkv);
    cudaGetSymbolAddress((void**)&attn_s,   g_attn);
    cudaGetSymbolAddress((void**)&xh_s,     g_xh);
    cudaGetSymbolAddress((void**)&wqkvT_s,  g_wqkvT);
    cudaGetSymbolAddress((void**)&wprojT_s, g_wprojT);

    cudaFuncSetAttribute(gemm_f16, cudaFuncAttributeMaxDynamicSharedMemorySize,
                         (int)GEMM_SMEM_BYTES);
    cudaFuncSetAttribute(attn_f16, cudaFuncAttributeMaxDynamicSharedMemorySize,
                         (int)ATTN_SMEM_BYTES);

    const int M = B_SZ * N_TOK;  // 8192

    // ---- fused pre-pass (single launch) ----
    prepass_kernel<<<PP_XBLKS + PP_WQBLKS + PP_WPBLKS, 256>>>(
        x, xh_s, w_qkv, wqkvT_s, w_proj, wprojT_s);

    // 1) qkv = x @ w_qkv  (fp16 out, Q cols pre-scaled)
    gemm_f16<<<dim3(3 * C_DIM / 128, M / 128), 256, GEMM_SMEM_BYTES>>>(
        xh_s, wqkvT_s, nullptr, qkv_s, M, 3 * C_DIM, C_DIM, 0, 1);

    // 2) fused Taylor attention -> fp16
    attn_f16<<<dim3(N_TOK / QROWS, B_SZ * H_NUM), 128, ATTN_SMEM_BYTES>>>(qkv_s, attn_s);

    // 3) out = attn @ w_proj + b_proj  (fp32 out)
    gemm_f16<<<dim3(C_DIM / 128, M / 128), 256, GEMM_SMEM_BYTES>>>(
        attn_s, wprojT_s, b_proj, out, M, C_DIM, C_DIM, 1, 0);
}